// round 8
// baseline (speedup 1.0000x reference)
#include <cuda_runtime.h>
#include <cuda_fp16.h>
#include <cstdint>
#include <cstddef>

#define NN    50000
#define EE    800000
#define ET    (EE + NN)
#define INC   128
#define HID   64
#define HEADS 5
#define CLS   40
#define L1F   (HEADS * HID)   // 320
#define L2F   (HEADS * CLS)   // 200
#define NB    ((NN + 255) / 256)

// ---------------- scratch ----------------------------------------------------
__device__ __half g_xh  [(size_t)NN * INC];        // x split hi
__device__ __half g_xl  [(size_t)NN * INC];        // x split lo
__device__ __half g_w0h [HID * INC];               // emb_W^T hi: [HID][INC]
__device__ __half g_w0l [HID * INC];               // emb_W^T lo
__device__ __half g_embh[(size_t)NN * HID];        // fp16 emb (A for layer-1 GEMM)
__device__ __half g_o1h [(size_t)NN * L1F];        // fp16 layer-1 out (A for layer-2 GEMM)
__device__ int4   g_hp16[(size_t)NN * L1F / 8];    // fp16 hp (reused both layers)
__device__ __half g_w1t [HID * L1F];               // W1^T fp16: [L1F][HID]
__device__ __half g_w2t [L1F * L2F];               // W2^T fp16: [L2F][L1F]
__device__ float  g_as1[NN * HEADS];
__device__ float  g_ad1[NN * HEADS];
__device__ float  g_as2[NN * HEADS];
__device__ float  g_ad2[NN * HEADS];
__device__ int    g_csrc[ET];
__device__ int    g_rowptr[NN + 1];
__device__ int    g_cnt[NN];
__device__ int    g_off[NN];
__device__ int    g_bsum[NB];
__device__ int    g_boff[NB];
__device__ int    g_is64;

// ---------------- dtype detect (parallel) ------------------------------------
__global__ void detect_dtype_k(const void* ei) {
    const int* p = (const int*)ei;
    int t = threadIdx.x;
    int nz = 0;
    for (int i = t; i < 1024; i += 32)
        if (p[2 * i + 1] != 0) nz = 1;
    unsigned m = __ballot_sync(0xFFFFFFFFu, nz);
    if (t == 0) g_is64 = (m == 0) ? 1 : 0;
}

__device__ __forceinline__ void edge_at(const void* ei, int i, int& s, int& d) {
    if (i < EE) {
        if (g_is64) {
            const long long* p = (const long long*)ei;
            s = (int)p[i];
            d = (int)p[EE + i];
        } else {
            const int* p = (const int*)ei;
            s = p[i];
            d = p[EE + i];
        }
    } else {
        s = i - EE;
        d = i - EE;
    }
}

__global__ void init_k() {
    int i = blockIdx.x * blockDim.x + threadIdx.x;
    if (i < NN) {
        g_cnt[i] = 0;
        g_off[i] = 0;
#pragma unroll
        for (int h = 0; h < HEADS; h++) {
            g_as1[i * HEADS + h] = 0.f;
            g_ad1[i * HEADS + h] = 0.f;
            g_as2[i * HEADS + h] = 0.f;
            g_ad2[i * HEADS + h] = 0.f;
        }
    }
}

// ---------------- combined convert kernel ------------------------------------
// segment 0: w1t [L1F][HID];  1: w2t [L2F][L1F];  2: w0h/w0l [HID][INC];  3: x split
#define SEG1 (HID * L1F)
#define SEG2 (SEG1 + L1F * L2F)
#define SEG3 (SEG2 + HID * INC)
#define SEGT (SEG3 + NN * INC)

__global__ void conv_k(const float* __restrict__ W1, const float* __restrict__ W2,
                       const float* __restrict__ W0, const float* __restrict__ x) {
    int i = blockIdx.x * blockDim.x + threadIdx.x;
    if (i >= SEGT) return;
    if (i < SEG1) {
        int n = i / HID, k = i % HID;
        g_w1t[i] = __float2half(W1[(size_t)k * L1F + n]);
    } else if (i < SEG2) {
        int j = i - SEG1;
        int n = j / L1F, k = j % L1F;
        g_w2t[j] = __float2half(W2[(size_t)k * L2F + n]);
    } else if (i < SEG3) {
        int j = i - SEG2;
        int n = j / INC, k = j % INC;
        float f = W0[(size_t)k * HID + n];
        __half h = __float2half_rn(f);
        g_w0h[j] = h;
        g_w0l[j] = __float2half_rn(f - __half2float(h));
    } else {
        int j = i - SEG3;
        float f = x[j];
        __half h = __float2half_rn(f);
        g_xh[j] = h;
        g_xl[j] = __float2half_rn(f - __half2float(h));
    }
}

// ---------------- CSR build ---------------------------------------------------
__global__ void hist_k(const void* ei) {
    int i = blockIdx.x * blockDim.x + threadIdx.x;
    if (i >= ET) return;
    int s, d;
    edge_at(ei, i, s, d);
    atomicAdd(&g_cnt[d], 1);
}

__global__ void blockscan_k() {
    __shared__ int sh[256];
    int b = blockIdx.x, t = threadIdx.x, i = b * 256 + t;
    int v = (i < NN) ? g_cnt[i] : 0;
    sh[t] = v;
    __syncthreads();
#pragma unroll
    for (int o = 1; o < 256; o <<= 1) {
        int u = (t >= o) ? sh[t - o] : 0;
        __syncthreads();
        sh[t] += u;
        __syncthreads();
    }
    if (i < NN) g_rowptr[i] = sh[t] - v;
    if (t == 255) g_bsum[b] = sh[255];
}

__global__ void bscan2_k() {
    __shared__ int sh[256];
    int t = threadIdx.x;
    int v = (t < NB) ? g_bsum[t] : 0;
    sh[t] = v;
    __syncthreads();
#pragma unroll
    for (int o = 1; o < 256; o <<= 1) {
        int u = (t >= o) ? sh[t - o] : 0;
        __syncthreads();
        sh[t] += u;
        __syncthreads();
    }
    if (t < NB) g_boff[t] = sh[t] - v;
}

__global__ void addoff_k() {
    int i = blockIdx.x * blockDim.x + threadIdx.x;
    if (i < NN) g_rowptr[i] += g_boff[i >> 8];
    if (i == 0) g_rowptr[NN] = ET;
}

__global__ void scatter_k(const void* ei) {
    int i = blockIdx.x * blockDim.x + threadIdx.x;
    if (i >= ET) return;
    int s, d;
    edge_at(ei, i, s, d);
    int pos = g_rowptr[d] + atomicAdd(&g_off[d], 1);
    g_csrc[pos] = s;
}

// ---------------- cp.async helpers -------------------------------------------
__device__ __forceinline__ void cp16h(__half* dst, const __half* src, bool pred) {
    uint32_t s = (uint32_t)__cvta_generic_to_shared(dst);
    int bytes = pred ? 16 : 0;
    asm volatile("cp.async.ca.shared.global [%0], [%1], 16, %2;\n"
                 :: "r"(s), "l"(src), "r"(bytes));
}
#define CP_COMMIT() asm volatile("cp.async.commit_group;\n" ::: "memory")
#define CP_WAIT(n)  asm volatile("cp.async.wait_group %0;\n" :: "n"(n) : "memory")

#define MMA16(cc, a, b)                                                         \
    asm volatile(                                                               \
        "mma.sync.aligned.m16n8k16.row.col.f32.f16.f16.f32 "                    \
        "{%0,%1,%2,%3},{%4,%5,%6,%7},{%8,%9},{%0,%1,%2,%3};\n"                  \
        : "+f"(cc[0]), "+f"(cc[1]), "+f"(cc[2]), "+f"(cc[3])                    \
        : "r"(a[0]), "r"(a[1]), "r"(a[2]), "r"(a[3]), "r"(b[0]), "r"(b[1]))

// ---------------- emb GEMM: fp16x3 (Ah,Al)@(Bh,Bl), fp32 + fp16 out ----------
// C = Ah*Bh + Ah*Bl + Al*Bh + bias.  M=NN, K=INC, N=HID.  grid (1, MB).
#define APL (128 * 40)
#define BPL (64 * 40)
#define STG (2 * APL + 2 * BPL)
#define EMB_SMEM (2 * STG * 2)

__global__ __launch_bounds__(256, 2)
void emb_gemm_k(const __half* __restrict__ Ah, const __half* __restrict__ Al,
                const __half* __restrict__ Bh, const __half* __restrict__ Bl,
                float* __restrict__ C, const float* __restrict__ bias,
                __half2* __restrict__ Ch, int M) {
    const int K = INC, Nc = HID;
    extern __shared__ __half smh[];
    int tid = threadIdx.x;
    int wid = tid >> 5, lane = tid & 31;
    int wm = wid & 3, wn = wid >> 2;
    int grp = lane >> 2, qid = lane & 3;
    int bm = blockIdx.y * 128;

    auto ldt = [&](int st, int k0) {
        __half* base = smh + st * STG;
        __half* Ahs = base;
        __half* Als = base + APL;
        __half* Bhs = base + 2 * APL;
        __half* Bls = base + 2 * APL + BPL;
#pragma unroll
        for (int t = 0; t < 2; t++) {
            int idx = tid + t * 256;
            int row = idx >> 2, c4 = idx & 3;
            int gm = bm + row;
            const __half* ga = Ah + (size_t)gm * K + k0 + c4 * 8;
            const __half* gl = Al + (size_t)gm * K + k0 + c4 * 8;
            cp16h(Ahs + row * 40 + c4 * 8, ga, gm < M);
            cp16h(Als + row * 40 + c4 * 8, gl, gm < M);
        }
        {
            int idx = tid;   // 256 = 64 rows x 4 chunks
            int n = idx >> 2, c4 = idx & 3;
            cp16h(Bhs + n * 40 + c4 * 8, Bh + (size_t)n * K + k0 + c4 * 8, true);
            cp16h(Bls + n * 40 + c4 * 8, Bl + (size_t)n * K + k0 + c4 * 8, true);
        }
    };

    float c[2][4][4] = {};
    const int nk = K >> 5;   // 4
    ldt(0, 0);
    CP_COMMIT();

    for (int t = 0; t < nk; t++) {
        if (t + 1 < nk) {
            ldt((t + 1) & 1, (t + 1) << 5);
            CP_COMMIT();
            CP_WAIT(1);
        } else {
            CP_WAIT(0);
        }
        __syncthreads();
        const __half* base = smh + (t & 1) * STG;
        const __half* Ahs = base;
        const __half* Als = base + APL;
        const __half* Bhs = base + 2 * APL;
        const __half* Bls = base + 2 * APL + BPL;
#pragma unroll
        for (int kk = 0; kk < 32; kk += 16) {
            uint32_t ah[2][4], al[2][4], bh[4][2], bl[4][2];
#pragma unroll
            for (int mi = 0; mi < 2; mi++) {
                int r = wm * 32 + mi * 16 + grp;
                ah[mi][0] = *(const uint32_t*)&Ahs[r * 40 + kk + 2 * qid];
                ah[mi][1] = *(const uint32_t*)&Ahs[(r + 8) * 40 + kk + 2 * qid];
                ah[mi][2] = *(const uint32_t*)&Ahs[r * 40 + kk + 2 * qid + 8];
                ah[mi][3] = *(const uint32_t*)&Ahs[(r + 8) * 40 + kk + 2 * qid + 8];
                al[mi][0] = *(const uint32_t*)&Als[r * 40 + kk + 2 * qid];
                al[mi][1] = *(const uint32_t*)&Als[(r + 8) * 40 + kk + 2 * qid];
                al[mi][2] = *(const uint32_t*)&Als[r * 40 + kk + 2 * qid + 8];
                al[mi][3] = *(const uint32_t*)&Als[(r + 8) * 40 + kk + 2 * qid + 8];
            }
#pragma unroll
            for (int ni = 0; ni < 4; ni++) {
                int cn = wn * 32 + ni * 8 + grp;
                bh[ni][0] = *(const uint32_t*)&Bhs[cn * 40 + kk + 2 * qid];
                bh[ni][1] = *(const uint32_t*)&Bhs[cn * 40 + kk + 2 * qid + 8];
                bl[ni][0] = *(const uint32_t*)&Bls[cn * 40 + kk + 2 * qid];
                bl[ni][1] = *(const uint32_t*)&Bls[cn * 40 + kk + 2 * qid + 8];
            }
#pragma unroll
            for (int mi = 0; mi < 2; mi++)
#pragma unroll
                for (int ni = 0; ni < 4; ni++) {
                    MMA16(c[mi][ni], ah[mi], bh[ni]);
                    MMA16(c[mi][ni], ah[mi], bl[ni]);
                    MMA16(c[mi][ni], al[mi], bh[ni]);
                }
        }
        __syncthreads();
    }

#pragma unroll
    for (int mi = 0; mi < 2; mi++) {
#pragma unroll
        for (int ni = 0; ni < 4; ni++) {
            int row = bm + wm * 32 + mi * 16 + grp;
            int col = wn * 32 + ni * 8 + 2 * qid;
            float bx = bias[col], by = bias[col + 1];
            float v0 = c[mi][ni][0] + bx, v1 = c[mi][ni][1] + by;
            float v2 = c[mi][ni][2] + bx, v3 = c[mi][ni][3] + by;
            if (row < M) {
                *(float2*)&C[(size_t)row * Nc + col] = make_float2(v0, v1);
                Ch[((size_t)row * Nc + col) / 2] = __floats2half2_rn(v0, v1);
            }
            if (row + 8 < M) {
                *(float2*)&C[(size_t)(row + 8) * Nc + col] = make_float2(v2, v3);
                Ch[((size_t)(row + 8) * Nc + col) / 2] = __floats2half2_rn(v2, v3);
            }
        }
    }
}

// ---------------- fp16 GAT GEMM (unchanged from R7) ---------------------------
template <int NT, int WN>
__global__ __launch_bounds__(256, 2)
void hgemm_k(const __half* __restrict__ A, const __half* __restrict__ Bt,
             int M, int K, int Nc,
             __half2* __restrict__ hp16,
             const float* __restrict__ att_s, const float* __restrict__ att_d,
             float* __restrict__ as_, float* __restrict__ ad_) {
    constexpr int WM = 8 / WN;
    constexpr int MI = 128 / (WM * 16);
    constexpr int NI = NT / (WN * 8);
    constexpr int NWC = NT / WN;
    constexpr int AST = 128 * 40;
    constexpr int BST = NT * 40;

    extern __shared__ __half smh[];
    __half* Asm = smh;
    __half* Bsm = smh + 2 * AST;
    int tid = threadIdx.x;
    int wid = tid >> 5, lane = tid & 31;
    int wm = wid % WM, wn = wid / WM;
    int grp = lane >> 2, qid = lane & 3;
    int bm = blockIdx.y * 128;
    int hidx = blockIdx.x;
    int bn = hidx * NT;

    auto ldt = [&](int b, int k0) {
        __half* Ab = Asm + b * AST;
        __half* Bb = Bsm + b * BST;
#pragma unroll
        for (int t = 0; t < 2; t++) {
            int idx = tid + t * 256;
            int row = idx >> 2, c4 = idx & 3;
            int gm = bm + row;
            cp16h(Ab + row * 40 + c4 * 8, A + (size_t)gm * K + k0 + c4 * 8, gm < M);
        }
#pragma unroll
        for (int t = 0; t < (NT * 4 + 255) / 256; t++) {
            int idx = tid + t * 256;
            if (idx < NT * 4) {
                int n = idx >> 2, c4 = idx & 3;
                cp16h(Bb + n * 40 + c4 * 8, Bt + (size_t)(bn + n) * K + k0 + c4 * 8, true);
            }
        }
    };

    float c[MI][NI][4] = {};
    int nk = K >> 5;
    ldt(0, 0);
    CP_COMMIT();

    for (int t = 0; t < nk; t++) {
        if (t + 1 < nk) {
            ldt((t + 1) & 1, (t + 1) << 5);
            CP_COMMIT();
            CP_WAIT(1);
        } else {
            CP_WAIT(0);
        }
        __syncthreads();
        const __half* Ab = Asm + (t & 1) * AST;
        const __half* Bb = Bsm + (t & 1) * BST;
#pragma unroll
        for (int kk = 0; kk < 32; kk += 16) {
            uint32_t a[MI][4], b[NI][2];
#pragma unroll
            for (int mi = 0; mi < MI; mi++) {
                int r = wm * (MI * 16) + mi * 16 + grp;
                a[mi][0] = *(const uint32_t*)&Ab[r * 40 + kk + 2 * qid];
                a[mi][1] = *(const uint32_t*)&Ab[(r + 8) * 40 + kk + 2 * qid];
                a[mi][2] = *(const uint32_t*)&Ab[r * 40 + kk + 2 * qid + 8];
                a[mi][3] = *(const uint32_t*)&Ab[(r + 8) * 40 + kk + 2 * qid + 8];
            }
#pragma unroll
            for (int ni = 0; ni < NI; ni++) {
                int cn = wn * NWC + ni * 8 + grp;
                b[ni][0] = *(const uint32_t*)&Bb[cn * 40 + kk + 2 * qid];
                b[ni][1] = *(const uint32_t*)&Bb[cn * 40 + kk + 2 * qid + 8];
            }
#pragma unroll
            for (int mi = 0; mi < MI; mi++)
#pragma unroll
                for (int ni = 0; ni < NI; ni++)
                    MMA16(c[mi][ni], a[mi], b[ni]);
        }
        __syncthreads();
    }

    const float* avs = att_s + hidx * NT;
    const float* avd = att_d + hidx * NT;
#pragma unroll
    for (int mi = 0; mi < MI; mi++) {
        int gr0 = bm + wm * (MI * 16) + mi * 16 + grp;
        int gr1 = gr0 + 8;
        float s0 = 0.f, d0 = 0.f, s1 = 0.f, d1 = 0.f;
#pragma unroll
        for (int ni = 0; ni < NI; ni++) {
            int colh = wn * NWC + ni * 8 + 2 * qid;
            float wsx = avs[colh], wsy = avs[colh + 1];
            float wdx = avd[colh], wdy = avd[colh + 1];
            s0 += c[mi][ni][0] * wsx + c[mi][ni][1] * wsy;
            d0 += c[mi][ni][0] * wdx + c[mi][ni][1] * wdy;
            s1 += c[mi][ni][2] * wsx + c[mi][ni][3] * wsy;
            d1 += c[mi][ni][2] * wdx + c[mi][ni][3] * wdy;
            __half2 h0 = __floats2half2_rn(c[mi][ni][0], c[mi][ni][1]);
            __half2 h1 = __floats2half2_rn(c[mi][ni][2], c[mi][ni][3]);
            int col = bn + colh;
            if (gr0 < M) hp16[((size_t)gr0 * Nc + col) / 2] = h0;
            if (gr1 < M) hp16[((size_t)gr1 * Nc + col) / 2] = h1;
        }
#pragma unroll
        for (int o = 1; o <= 2; o <<= 1) {
            s0 += __shfl_xor_sync(0xFFFFFFFFu, s0, o);
            d0 += __shfl_xor_sync(0xFFFFFFFFu, d0, o);
            s1 += __shfl_xor_sync(0xFFFFFFFFu, s1, o);
            d1 += __shfl_xor_sync(0xFFFFFFFFu, d1, o);
        }
        if (qid == 0) {
            if (gr0 < M) {
                atomicAdd(&as_[gr0 * HEADS + hidx], s0);
                atomicAdd(&ad_[gr0 * HEADS + hidx], d0);
            }
            if (gr1 < M) {
                atomicAdd(&as_[gr1 * HEADS + hidx], s1);
                atomicAdd(&ad_[gr1 * HEADS + hidx], d1);
            }
        }
    }
}

// ---------------- layer-1 aggregation (chunk preload + shfl) ------------------
__global__ void gat_aggr1_k(const int4* __restrict__ hp16,
                            const float* __restrict__ as_,
                            const float* __restrict__ ad_,
                            const float* __restrict__ bias,
                            __half* __restrict__ out) {
    const int C = HID, F = L1F, NO8 = F / 8;     // 40 octets
    int w = (blockIdx.x * blockDim.x + threadIdx.x) >> 5;
    int lane = threadIdx.x & 31;
    if (w >= NN) return;
    int r0 = g_rowptr[w], r1 = g_rowptr[w + 1];

    const int o0 = lane, o1 = lane + 32;
    const bool v1 = o1 < NO8;
    const int h0 = (o0 * 8) / C;
    const int h1 = v1 ? (o1 * 8) / C : 0;
    const float adv0 = ad_[w * HEADS + h0];
    const float adv1 = v1 ? ad_[w * HEADS + h1] : 0.f;

    float acc0[8] = {}, acc1[8] = {};
    float sl0 = 0.f, sl1 = 0.f;

    for (int jb = r0; jb < r1; jb += 32) {
        int j = jb + lane;
        int smy = (j < r1) ? __ldg(&g_csrc[j]) : 0;
        int cnt = min(32, r1 - jb);
#pragma unroll 4
        for (int k = 0; k < cnt; k++) {
            int s = __shfl_sync(0xFFFFFFFFu, smy, k);
            const int4* row = hp16 + (size_t)s * NO8;
            {
                float e = __ldg(&as_[s * HEADS + h0]) + adv0;
                e = (e > 0.f) ? e : 0.2f * e;
                float a = __expf(e);
                sl0 += a;
                int4 p = __ldg(row + o0);
                float2 f0 = __half22float2(*(__half2*)&p.x);
                float2 f1 = __half22float2(*(__half2*)&p.y);
                float2 f2 = __half22float2(*(__half2*)&p.z);
                float2 f3 = __half22float2(*(__half2*)&p.w);
                acc0[0] += a * f0.x; acc0[1] += a * f0.y;
                acc0[2] += a * f1.x; acc0[3] += a * f1.y;
                acc0[4] += a * f2.x; acc0[5] += a * f2.y;
                acc0[6] += a * f3.x; acc0[7] += a * f3.y;
            }
            if (v1) {
                float e = __ldg(&as_[s * HEADS + h1]) + adv1;
                e = (e > 0.f) ? e : 0.2f * e;
                float a = __expf(e);
                sl1 += a;
                int4 p = __ldg(row + o1);
                float2 f0 = __half22float2(*(__half2*)&p.x);
                float2 f1 = __half22float2(*(__half2*)&p.y);
                float2 f2 = __half22float2(*(__half2*)&p.z);
                float2 f3 = __half22float2(*(__half2*)&p.w);
                acc1[0] += a * f0.x; acc1[1] += a * f0.y;
                acc1[2] += a * f1.x; acc1[3] += a * f1.y;
                acc1[4] += a * f2.x; acc1[5] += a * f2.y;
                acc1[6] += a * f3.x; acc1[7] += a * f3.y;
            }
        }
    }

    {
        float inv = 1.f / (sl0 + 1e-16f);
        __half2 hh[4];
#pragma unroll
        for (int k = 0; k < 4; k++) {
            float va = acc0[2 * k] * inv + bias[o0 * 8 + 2 * k];
            float vb = acc0[2 * k + 1] * inv + bias[o0 * 8 + 2 * k + 1];
            va = (va > 0.f) ? va : (__expf(va) - 1.f);
            vb = (vb > 0.f) ? vb : (__expf(vb) - 1.f);
            hh[k] = __floats2half2_rn(va, vb);
        }
        int4 st;
        st.x = *(int*)&hh[0]; st.y = *(int*)&hh[1];
        st.z = *(int*)&hh[2]; st.w = *(int*)&hh[3];
        *(int4*)(out + (size_t)w * F + o0 * 8) = st;
    }
    if (v1) {
        float inv = 1.f / (sl1 + 1e-16f);
        __half2 hh[4];
#pragma unroll
        for (int k = 0; k < 4; k++) {
            float va = acc1[2 * k] * inv + bias[o1 * 8 + 2 * k];
            float vb = acc1[2 * k + 1] * inv + bias[o1 * 8 + 2 * k + 1];
            va = (va > 0.f) ? va : (__expf(va) - 1.f);
            vb = (vb > 0.f) ? vb : (__expf(vb) - 1.f);
            hh[k] = __floats2half2_rn(va, vb);
        }
        int4 st;
        st.x = *(int*)&hh[0]; st.y = *(int*)&hh[1];
        st.z = *(int*)&hh[2]; st.w = *(int*)&hh[3];
        *(int4*)(out + (size_t)w * F + o1 * 8) = st;
    }
}

// ---------------- layer-2 aggregation + head-mean + log_softmax --------------
__global__ void gat_aggr2fin_k(const int4* __restrict__ hp16,
                               const float* __restrict__ as_,
                               const float* __restrict__ ad_,
                               const float* __restrict__ b2,
                               float* __restrict__ logits) {
    const int C = CLS, NO8 = L2F / 8;            // 25 octets
    __shared__ float sh[8][L2F];
    int w = (blockIdx.x * blockDim.x + threadIdx.x) >> 5;
    int wl = threadIdx.x >> 5;
    int lane = threadIdx.x & 31;
    if (w >= NN) return;
    int r0 = g_rowptr[w], r1 = g_rowptr[w + 1];

    const int o0 = lane;
    const bool v0 = o0 < NO8;
    const int h0 = v0 ? (o0 * 8) / C : 0;
    const float adv0 = v0 ? ad_[w * HEADS + h0] : 0.f;

    float acc0[8] = {};
    float sl0 = 0.f;

    for (int jb = r0; jb < r1; jb += 32) {
        int j = jb + lane;
        int smy = (j < r1) ? __ldg(&g_csrc[j]) : 0;
        int cnt = min(32, r1 - jb);
#pragma unroll 4
        for (int k = 0; k < cnt; k++) {
            int s = __shfl_sync(0xFFFFFFFFu, smy, k);
            if (v0) {
                float e = __ldg(&as_[s * HEADS + h0]) + adv0;
                e = (e > 0.f) ? e : 0.2f * e;
                float a = __expf(e);
                sl0 += a;
                int4 p = __ldg(hp16 + (size_t)s * NO8 + o0);
                float2 f0 = __half22float2(*(__half2*)&p.x);
                float2 f1 = __half22float2(*(__half2*)&p.y);
                float2 f2 = __half22float2(*(__half2*)&p.z);
                float2 f3 = __half22float2(*(__half2*)&p.w);
                acc0[0] += a * f0.x; acc0[1] += a * f0.y;
                acc0[2] += a * f1.x; acc0[3] += a * f1.y;
                acc0[4] += a * f2.x; acc0[5] += a * f2.y;
                acc0[6] += a * f3.x; acc0[7] += a * f3.y;
            }
        }
    }

    if (v0) {
        float inv = 1.f / (sl0 + 1e-16f);
#pragma unroll
        for (int k = 0; k < 8; k++) sh[wl][o0 * 8 + k] = acc0[k] * inv;
    }
    __syncwarp();

    int c0 = lane, c1 = lane + 32;
    bool has1 = (c1 < CLS);
    float a0 = 0.f, a1 = 0.f;
#pragma unroll
    for (int h = 0; h < HEADS; h++) a0 += sh[wl][h * CLS + c0];
    float v0f = a0 * (1.f / HEADS) + b2[c0];
    float v1f = 0.f;
    if (has1) {
#pragma unroll
        for (int h = 0; h < HEADS; h++) a1 += sh[wl][h * CLS + c1];
        v1f = a1 * (1.f / HEADS) + b2[c1];
    }
    float mx = has1 ? fmaxf(v0f, v1f) : v0f;
#pragma unroll
    for (int o = 16; o; o >>= 1) mx = fmaxf(mx, __shfl_xor_sync(0xFFFFFFFFu, mx, o));
    float se = __expf(v0f - mx) + (has1 ? __expf(v1f - mx) : 0.f);
#pragma unroll
    for (int o = 16; o; o >>= 1) se += __shfl_xor_sync(0xFFFFFFFFu, se, o);
    float lse = logf(se) + mx;
    logits[(size_t)w * CLS + c0] = v0f - lse;
    if (has1) logits[(size_t)w * CLS + c1] = v1f - lse;
}

// ---------------- host --------------------------------------------------------
#define HSMEM_NT64 ((2 * 128 * 40 + 2 * 64 * 40) * 2)
#define HSMEM_NT40 ((2 * 128 * 40 + 2 * 40 * 40) * 2)

extern "C" void kernel_launch(void* const* d_in, const int* in_sizes, int n_in,
                              void* d_out, int out_size) {
    const float* x     = (const float*)d_in[0];
    const void*  ei    = d_in[1];
    const float* emb_W = (const float*)d_in[2];
    const float* emb_b = (const float*)d_in[3];
    const float* W1    = (const float*)d_in[4];
    const float* at_s1 = (const float*)d_in[5];
    const float* at_d1 = (const float*)d_in[6];
    const float* b1    = (const float*)d_in[7];
    const float* W2    = (const float*)d_in[8];
    const float* at_s2 = (const float*)d_in[9];
    const float* at_d2 = (const float*)d_in[10];
    const float* b2    = (const float*)d_in[11];

    float* outp   = (float*)d_out;
    float* emb    = outp;
    float* logits = outp + (size_t)NN * HID;

    float *as1, *ad1, *as2, *ad2;
    __half *embh, *o1h, *w1t, *w2t, *xh, *xl, *w0h, *w0l;
    int4* hp16;
    cudaGetSymbolAddress((void**)&as1,  g_as1);
    cudaGetSymbolAddress((void**)&ad1,  g_ad1);
    cudaGetSymbolAddress((void**)&as2,  g_as2);
    cudaGetSymbolAddress((void**)&ad2,  g_ad2);
    cudaGetSymbolAddress((void**)&embh, g_embh);
    cudaGetSymbolAddress((void**)&o1h,  g_o1h);
    cudaGetSymbolAddress((void**)&w1t,  g_w1t);
    cudaGetSymbolAddress((void**)&w2t,  g_w2t);
    cudaGetSymbolAddress((void**)&xh,   g_xh);
    cudaGetSymbolAddress((void**)&xl,   g_xl);
    cudaGetSymbolAddress((void**)&w0h,  g_w0h);
    cudaGetSymbolAddress((void**)&w0l,  g_w0l);
    cudaGetSymbolAddress((void**)&hp16, g_hp16);

    cudaFuncSetAttribute(emb_gemm_k, cudaFuncAttributeMaxDynamicSharedMemorySize, EMB_SMEM);
    cudaFuncSetAttribute(hgemm_k<64, 2>, cudaFuncAttributeMaxDynamicSharedMemorySize, HSMEM_NT64);
    cudaFuncSetAttribute(hgemm_k<40, 1>, cudaFuncAttributeMaxDynamicSharedMemorySize, HSMEM_NT40);

    const int T = 256;
    const int MB = (NN + 127) / 128;

    // 0..4
    detect_dtype_k<<<1, 32>>>(ei);
    conv_k<<<(SEGT + T - 1) / T, T>>>(W1, W2, emb_W, x);
    init_k<<<(NN + T - 1) / T, T>>>();
    hist_k<<<(ET + T - 1) / T, T>>>(ei);
    blockscan_k<<<NB, 256>>>();

    // 5: emb fp16x3 GEMM (profiled at ncu -s 5)
    emb_gemm_k<<<dim3(1, MB), 256, EMB_SMEM>>>(
        xh, xl, w0h, w0l, emb, emb_b, (__half2*)embh, NN);

    hgemm_k<64, 2><<<dim3(HEADS, MB), 256, HSMEM_NT64>>>(
        embh, w1t, NN, HID, L1F, (__half2*)hp16, at_s1, at_d1, as1, ad1);

    bscan2_k<<<1, 256>>>();
    addoff_k<<<(NN + T - 1) / T, T>>>();
    scatter_k<<<(ET + T - 1) / T, T>>>(ei);

    gat_aggr1_k<<<(NN * 32 + T - 1) / T, T>>>(hp16, as1, ad1, b1, o1h);

    hgemm_k<40, 1><<<dim3(HEADS, MB), 256, HSMEM_NT40>>>(
        o1h, w2t, NN, L1F, L2F, (__half2*)hp16, at_s2, at_d2, as2, ad2);

    gat_aggr2fin_k<<<(NN * 32 + T - 1) / T, T>>>(hp16, as2, ad2, b2, logits);
}

// round 9
// speedup vs baseline: 1.0138x; 1.0138x over previous
#include <cuda_runtime.h>
#include <cuda_fp16.h>
#include <cstdint>
#include <cstddef>

#define NN    50000
#define EE    800000
#define ET    (EE + NN)
#define INC   128
#define HID   64
#define HEADS 5
#define CLS   40
#define L1F   (HEADS * HID)   // 320
#define L2F   (HEADS * CLS)   // 200
#define NB    ((NN + 255) / 256)

// ---------------- scratch ----------------------------------------------------
__device__ __half g_xh  [(size_t)NN * INC];
__device__ __half g_xl  [(size_t)NN * INC];
__device__ __half g_w0h [HID * INC];
__device__ __half g_w0l [HID * INC];
__device__ __half g_embh[(size_t)NN * HID];
__device__ __half g_o1h [(size_t)NN * L1F];
__device__ int4   g_hp16[(size_t)NN * L1F / 8];
__device__ __half g_w1t [HID * L1F];
__device__ __half g_w2t [L1F * L2F];
__device__ float  g_as1[NN * HEADS];
__device__ float  g_ad1[NN * HEADS];
__device__ float  g_as2[NN * HEADS];
__device__ float  g_ad2[NN * HEADS];
__device__ int    g_csrc[ET];
__device__ int    g_rowptr[NN + 1];
__device__ int    g_cnt[NN];
__device__ int    g_off[NN];
__device__ int    g_bsum[NB];
__device__ int    g_boff[NB];
__device__ int    g_is64;

// ---------------- dtype detect ------------------------------------------------
__global__ void detect_dtype_k(const void* ei) {
    const int* p = (const int*)ei;
    int t = threadIdx.x;
    int nz = 0;
    for (int i = t; i < 1024; i += 32)
        if (p[2 * i + 1] != 0) nz = 1;
    unsigned m = __ballot_sync(0xFFFFFFFFu, nz);
    if (t == 0) g_is64 = (m == 0) ? 1 : 0;
}

__device__ __forceinline__ void edge_at(const void* ei, int i, int& s, int& d) {
    if (i < EE) {
        if (g_is64) {
            const long long* p = (const long long*)ei;
            s = (int)p[i];
            d = (int)p[EE + i];
        } else {
            const int* p = (const int*)ei;
            s = p[i];
            d = p[EE + i];
        }
    } else {
        s = i - EE;
        d = i - EE;
    }
}

// ---------------- prep: conv + init + hist (one kernel) -----------------------
#define SEG1 (HID * L1F)
#define SEG2 (SEG1 + L1F * L2F)
#define SEG3 (SEG2 + HID * INC)
#define SEGT (SEG3 + NN * INC)

__global__ void prep_k(const void* ei,
                       const float* __restrict__ W1, const float* __restrict__ W2,
                       const float* __restrict__ W0, const float* __restrict__ x) {
    int i = blockIdx.x * blockDim.x + threadIdx.x;
    // conversions
    if (i < SEG1) {
        int n = i / HID, k = i % HID;
        g_w1t[i] = __float2half(W1[(size_t)k * L1F + n]);
    } else if (i < SEG2) {
        int j = i - SEG1;
        int n = j / L1F, k = j % L1F;
        g_w2t[j] = __float2half(W2[(size_t)k * L2F + n]);
    } else if (i < SEG3) {
        int j = i - SEG2;
        int n = j / INC, k = j % INC;
        float f = W0[(size_t)k * HID + n];
        __half h = __float2half_rn(f);
        g_w0h[j] = h;
        g_w0l[j] = __float2half_rn(f - __half2float(h));
    } else if (i < SEGT) {
        int j = i - SEG3;
        float f = x[j];
        __half h = __float2half_rn(f);
        g_xh[j] = h;
        g_xl[j] = __float2half_rn(f - __half2float(h));
    }
    // init
    if (i < NN) {
        g_cnt[i] = 0;   // histogram below uses atomics on g_cnt of OTHER indices;
    }
    __syncthreads();    // no cross-block guarantee; do hist in second grid-stride below
    // NOTE: histogram must not race with g_cnt init. Since init writes g_cnt[i]=0
    // only for i<NN and histogram atomics may target any dst from any block, we
    // CANNOT safely histogram here. Histogram is done in hist_k (separate launch).
    if (i < NN) {
        g_off[i] = 0;
#pragma unroll
        for (int h = 0; h < HEADS; h++) {
            g_as1[i * HEADS + h] = 0.f;
            g_ad1[i * HEADS + h] = 0.f;
            g_as2[i * HEADS + h] = 0.f;
            g_ad2[i * HEADS + h] = 0.f;
        }
    }
}

__global__ void hist_k(const void* ei) {
    int i = blockIdx.x * blockDim.x + threadIdx.x;
    if (i >= ET) return;
    int s, d;
    edge_at(ei, i, s, d);
    atomicAdd(&g_cnt[d], 1);
}

// ---------------- parallel scan ------------------------------------------------
__global__ void blockscan_k() {
    __shared__ int sh[256];
    int b = blockIdx.x, t = threadIdx.x, i = b * 256 + t;
    int v = (i < NN) ? g_cnt[i] : 0;
    sh[t] = v;
    __syncthreads();
#pragma unroll
    for (int o = 1; o < 256; o <<= 1) {
        int u = (t >= o) ? sh[t - o] : 0;
        __syncthreads();
        sh[t] += u;
        __syncthreads();
    }
    if (i < NN) g_rowptr[i] = sh[t] - v;
    if (t == 255) g_bsum[b] = sh[255];
}

__global__ void bscan2_k() {
    __shared__ int sh[256];
    int t = threadIdx.x;
    int v = (t < NB) ? g_bsum[t] : 0;
    sh[t] = v;
    __syncthreads();
#pragma unroll
    for (int o = 1; o < 256; o <<= 1) {
        int u = (t >= o) ? sh[t - o] : 0;
        __syncthreads();
        sh[t] += u;
        __syncthreads();
    }
    if (t < NB) g_boff[t] = sh[t] - v;
}

__global__ void addoff_k() {
    int i = blockIdx.x * blockDim.x + threadIdx.x;
    if (i < NN) g_rowptr[i] += g_boff[i >> 8];
    if (i == 0) g_rowptr[NN] = ET;
}

__global__ void scatter_k(const void* ei) {
    int i = blockIdx.x * blockDim.x + threadIdx.x;
    if (i >= ET) return;
    int s, d;
    edge_at(ei, i, s, d);
    int pos = g_rowptr[d] + atomicAdd(&g_off[d], 1);
    g_csrc[pos] = s;
}

// ---------------- cp.async helpers --------------------------------------------
__device__ __forceinline__ void cp16h(__half* dst, const __half* src, bool pred) {
    uint32_t s = (uint32_t)__cvta_generic_to_shared(dst);
    int bytes = pred ? 16 : 0;
    asm volatile("cp.async.ca.shared.global [%0], [%1], 16, %2;\n"
                 :: "r"(s), "l"(src), "r"(bytes));
}
#define CP_COMMIT() asm volatile("cp.async.commit_group;\n" ::: "memory")
#define CP_WAIT(n)  asm volatile("cp.async.wait_group %0;\n" :: "n"(n) : "memory")

#define MMA16(cc, a, b)                                                         \
    asm volatile(                                                               \
        "mma.sync.aligned.m16n8k16.row.col.f32.f16.f16.f32 "                    \
        "{%0,%1,%2,%3},{%4,%5,%6,%7},{%8,%9},{%0,%1,%2,%3};\n"                  \
        : "+f"(cc[0]), "+f"(cc[1]), "+f"(cc[2]), "+f"(cc[3])                    \
        : "r"(a[0]), "r"(a[1]), "r"(a[2]), "r"(a[3]), "r"(b[0]), "r"(b[1]))

// ---------------- emb GEMM: fp16x3 --------------------------------------------
#define APL (128 * 40)
#define BPL (64 * 40)
#define STG (2 * APL + 2 * BPL)
#define EMB_SMEM (2 * STG * 2)

__global__ __launch_bounds__(256, 2)
void emb_gemm_k(const __half* __restrict__ Ah, const __half* __restrict__ Al,
                const __half* __restrict__ Bh, const __half* __restrict__ Bl,
                float* __restrict__ C, const float* __restrict__ bias,
                __half2* __restrict__ Ch, int M) {
    const int K = INC, Nc = HID;
    extern __shared__ __half smh[];
    int tid = threadIdx.x;
    int wid = tid >> 5, lane = tid & 31;
    int wm = wid & 3, wn = wid >> 2;
    int grp = lane >> 2, qid = lane & 3;
    int bm = blockIdx.y * 128;

    auto ldt = [&](int st, int k0) {
        __half* base = smh + st * STG;
        __half* Ahs = base;
        __half* Als = base + APL;
        __half* Bhs = base + 2 * APL;
        __half* Bls = base + 2 * APL + BPL;
#pragma unroll
        for (int t = 0; t < 2; t++) {
            int idx = tid + t * 256;
            int row = idx >> 2, c4 = idx & 3;
            int gm = bm + row;
            cp16h(Ahs + row * 40 + c4 * 8, Ah + (size_t)gm * K + k0 + c4 * 8, gm < M);
            cp16h(Als + row * 40 + c4 * 8, Al + (size_t)gm * K + k0 + c4 * 8, gm < M);
        }
        {
            int n = tid >> 2, c4 = tid & 3;
            cp16h(Bhs + n * 40 + c4 * 8, Bh + (size_t)n * K + k0 + c4 * 8, true);
            cp16h(Bls + n * 40 + c4 * 8, Bl + (size_t)n * K + k0 + c4 * 8, true);
        }
    };

    float c[2][4][4] = {};
    const int nk = K >> 5;
    ldt(0, 0);
    CP_COMMIT();

    for (int t = 0; t < nk; t++) {
        if (t + 1 < nk) {
            ldt((t + 1) & 1, (t + 1) << 5);
            CP_COMMIT();
            CP_WAIT(1);
        } else {
            CP_WAIT(0);
        }
        __syncthreads();
        const __half* base = smh + (t & 1) * STG;
        const __half* Ahs = base;
        const __half* Als = base + APL;
        const __half* Bhs = base + 2 * APL;
        const __half* Bls = base + 2 * APL + BPL;
#pragma unroll
        for (int kk = 0; kk < 32; kk += 16) {
            uint32_t ah[2][4], al[2][4], bh[4][2], bl[4][2];
#pragma unroll
            for (int mi = 0; mi < 2; mi++) {
                int r = wm * 32 + mi * 16 + grp;
                ah[mi][0] = *(const uint32_t*)&Ahs[r * 40 + kk + 2 * qid];
                ah[mi][1] = *(const uint32_t*)&Ahs[(r + 8) * 40 + kk + 2 * qid];
                ah[mi][2] = *(const uint32_t*)&Ahs[r * 40 + kk + 2 * qid + 8];
                ah[mi][3] = *(const uint32_t*)&Ahs[(r + 8) * 40 + kk + 2 * qid + 8];
                al[mi][0] = *(const uint32_t*)&Als[r * 40 + kk + 2 * qid];
                al[mi][1] = *(const uint32_t*)&Als[(r + 8) * 40 + kk + 2 * qid];
                al[mi][2] = *(const uint32_t*)&Als[r * 40 + kk + 2 * qid + 8];
                al[mi][3] = *(const uint32_t*)&Als[(r + 8) * 40 + kk + 2 * qid + 8];
            }
#pragma unroll
            for (int ni = 0; ni < 4; ni++) {
                int cn = wn * 32 + ni * 8 + grp;
                bh[ni][0] = *(const uint32_t*)&Bhs[cn * 40 + kk + 2 * qid];
                bh[ni][1] = *(const uint32_t*)&Bhs[cn * 40 + kk + 2 * qid + 8];
                bl[ni][0] = *(const uint32_t*)&Bls[cn * 40 + kk + 2 * qid];
                bl[ni][1] = *(const uint32_t*)&Bls[cn * 40 + kk + 2 * qid + 8];
            }
#pragma unroll
            for (int mi = 0; mi < 2; mi++)
#pragma unroll
                for (int ni = 0; ni < 4; ni++) {
                    MMA16(c[mi][ni], ah[mi], bh[ni]);
                    MMA16(c[mi][ni], ah[mi], bl[ni]);
                    MMA16(c[mi][ni], al[mi], bh[ni]);
                }
        }
        __syncthreads();
    }

#pragma unroll
    for (int mi = 0; mi < 2; mi++) {
#pragma unroll
        for (int ni = 0; ni < 4; ni++) {
            int row = bm + wm * 32 + mi * 16 + grp;
            int col = wn * 32 + ni * 8 + 2 * qid;
            float bx = bias[col], by = bias[col + 1];
            float v0 = c[mi][ni][0] + bx, v1 = c[mi][ni][1] + by;
            float v2 = c[mi][ni][2] + bx, v3 = c[mi][ni][3] + by;
            if (row < M) {
                *(float2*)&C[(size_t)row * Nc + col] = make_float2(v0, v1);
                Ch[((size_t)row * Nc + col) / 2] = __floats2half2_rn(v0, v1);
            }
            if (row + 8 < M) {
                *(float2*)&C[(size_t)(row + 8) * Nc + col] = make_float2(v2, v3);
                Ch[((size_t)(row + 8) * Nc + col) / 2] = __floats2half2_rn(v2, v3);
            }
        }
    }
}

// ---------------- fp16 GAT GEMM -----------------------------------------------
template <int NT, int WN>
__global__ __launch_bounds__(256, 2)
void hgemm_k(const __half* __restrict__ A, const __half* __restrict__ Bt,
             int M, int K, int Nc,
             __half2* __restrict__ hp16,
             const float* __restrict__ att_s, const float* __restrict__ att_d,
             float* __restrict__ as_, float* __restrict__ ad_) {
    constexpr int WM = 8 / WN;
    constexpr int MI = 128 / (WM * 16);
    constexpr int NI = NT / (WN * 8);
    constexpr int NWC = NT / WN;
    constexpr int AST = 128 * 40;
    constexpr int BST = NT * 40;

    extern __shared__ __half smh[];
    __half* Asm = smh;
    __half* Bsm = smh + 2 * AST;
    int tid = threadIdx.x;
    int wid = tid >> 5, lane = tid & 31;
    int wm = wid % WM, wn = wid / WM;
    int grp = lane >> 2, qid = lane & 3;
    int bm = blockIdx.y * 128;
    int hidx = blockIdx.x;
    int bn = hidx * NT;

    auto ldt = [&](int b, int k0) {
        __half* Ab = Asm + b * AST;
        __half* Bb = Bsm + b * BST;
#pragma unroll
        for (int t = 0; t < 2; t++) {
            int idx = tid + t * 256;
            int row = idx >> 2, c4 = idx & 3;
            int gm = bm + row;
            cp16h(Ab + row * 40 + c4 * 8, A + (size_t)gm * K + k0 + c4 * 8, gm < M);
        }
#pragma unroll
        for (int t = 0; t < (NT * 4 + 255) / 256; t++) {
            int idx = tid + t * 256;
            if (idx < NT * 4) {
                int n = idx >> 2, c4 = idx & 3;
                cp16h(Bb + n * 40 + c4 * 8, Bt + (size_t)(bn + n) * K + k0 + c4 * 8, true);
            }
        }
    };

    float c[MI][NI][4] = {};
    int nk = K >> 5;
    ldt(0, 0);
    CP_COMMIT();

    for (int t = 0; t < nk; t++) {
        if (t + 1 < nk) {
            ldt((t + 1) & 1, (t + 1) << 5);
            CP_COMMIT();
            CP_WAIT(1);
        } else {
            CP_WAIT(0);
        }
        __syncthreads();
        const __half* Ab = Asm + (t & 1) * AST;
        const __half* Bb = Bsm + (t & 1) * BST;
#pragma unroll
        for (int kk = 0; kk < 32; kk += 16) {
            uint32_t a[MI][4], b[NI][2];
#pragma unroll
            for (int mi = 0; mi < MI; mi++) {
                int r = wm * (MI * 16) + mi * 16 + grp;
                a[mi][0] = *(const uint32_t*)&Ab[r * 40 + kk + 2 * qid];
                a[mi][1] = *(const uint32_t*)&Ab[(r + 8) * 40 + kk + 2 * qid];
                a[mi][2] = *(const uint32_t*)&Ab[r * 40 + kk + 2 * qid + 8];
                a[mi][3] = *(const uint32_t*)&Ab[(r + 8) * 40 + kk + 2 * qid + 8];
            }
#pragma unroll
            for (int ni = 0; ni < NI; ni++) {
                int cn = wn * NWC + ni * 8 + grp;
                b[ni][0] = *(const uint32_t*)&Bb[cn * 40 + kk + 2 * qid];
                b[ni][1] = *(const uint32_t*)&Bb[cn * 40 + kk + 2 * qid + 8];
            }
#pragma unroll
            for (int mi = 0; mi < MI; mi++)
#pragma unroll
                for (int ni = 0; ni < NI; ni++)
                    MMA16(c[mi][ni], a[mi], b[ni]);
        }
        __syncthreads();
    }

    const float* avs = att_s + hidx * NT;
    const float* avd = att_d + hidx * NT;
#pragma unroll
    for (int mi = 0; mi < MI; mi++) {
        int gr0 = bm + wm * (MI * 16) + mi * 16 + grp;
        int gr1 = gr0 + 8;
        float s0 = 0.f, d0 = 0.f, s1 = 0.f, d1 = 0.f;
#pragma unroll
        for (int ni = 0; ni < NI; ni++) {
            int colh = wn * NWC + ni * 8 + 2 * qid;
            float wsx = avs[colh], wsy = avs[colh + 1];
            float wdx = avd[colh], wdy = avd[colh + 1];
            s0 += c[mi][ni][0] * wsx + c[mi][ni][1] * wsy;
            d0 += c[mi][ni][0] * wdx + c[mi][ni][1] * wdy;
            s1 += c[mi][ni][2] * wsx + c[mi][ni][3] * wsy;
            d1 += c[mi][ni][2] * wdx + c[mi][ni][3] * wdy;
            __half2 h0 = __floats2half2_rn(c[mi][ni][0], c[mi][ni][1]);
            __half2 h1 = __floats2half2_rn(c[mi][ni][2], c[mi][ni][3]);
            int col = bn + colh;
            if (gr0 < M) hp16[((size_t)gr0 * Nc + col) / 2] = h0;
            if (gr1 < M) hp16[((size_t)gr1 * Nc + col) / 2] = h1;
        }
#pragma unroll
        for (int o = 1; o <= 2; o <<= 1) {
            s0 += __shfl_xor_sync(0xFFFFFFFFu, s0, o);
            d0 += __shfl_xor_sync(0xFFFFFFFFu, d0, o);
            s1 += __shfl_xor_sync(0xFFFFFFFFu, s1, o);
            d1 += __shfl_xor_sync(0xFFFFFFFFu, d1, o);
        }
        if (qid == 0) {
            if (gr0 < M) {
                atomicAdd(&as_[gr0 * HEADS + hidx], s0);
                atomicAdd(&ad_[gr0 * HEADS + hidx], d0);
            }
            if (gr1 < M) {
                atomicAdd(&as_[gr1 * HEADS + hidx], s1);
                atomicAdd(&ad_[gr1 * HEADS + hidx], d1);
            }
        }
    }
}

// ---------------- layer-1 aggregation (R7 direct-loop form) --------------------
__global__ void gat_aggr1_k(const int4* __restrict__ hp16,
                            const float* __restrict__ as_,
                            const float* __restrict__ ad_,
                            const float* __restrict__ bias,
                            __half* __restrict__ out) {
    const int C = HID, F = L1F, NO8 = F / 8;
    int w = (blockIdx.x * blockDim.x + threadIdx.x) >> 5;
    int lane = threadIdx.x & 31;
    if (w >= NN) return;
    int r0 = g_rowptr[w], r1 = g_rowptr[w + 1];

    const int o0 = lane, o1 = lane + 32;
    const bool v1 = o1 < NO8;
    const int h0 = (o0 * 8) / C;
    const int h1 = v1 ? (o1 * 8) / C : 0;
    const float adv0 = ad_[w * HEADS + h0];
    const float adv1 = v1 ? ad_[w * HEADS + h1] : 0.f;

    float acc0[8] = {}, acc1[8] = {};
    float sl0 = 0.f, sl1 = 0.f;

#pragma unroll 4
    for (int j = r0; j < r1; j++) {
        int s = __ldg(&g_csrc[j]);
        const int4* row = hp16 + (size_t)s * NO8;
        {
            float e = __ldg(&as_[s * HEADS + h0]) + adv0;
            e = (e > 0.f) ? e : 0.2f * e;
            float a = __expf(e);
            sl0 += a;
            int4 p = __ldg(row + o0);
            float2 f0 = __half22float2(*(__half2*)&p.x);
            float2 f1 = __half22float2(*(__half2*)&p.y);
            float2 f2 = __half22float2(*(__half2*)&p.z);
            float2 f3 = __half22float2(*(__half2*)&p.w);
            acc0[0] += a * f0.x; acc0[1] += a * f0.y;
            acc0[2] += a * f1.x; acc0[3] += a * f1.y;
            acc0[4] += a * f2.x; acc0[5] += a * f2.y;
            acc0[6] += a * f3.x; acc0[7] += a * f3.y;
        }
        if (v1) {
            float e = __ldg(&as_[s * HEADS + h1]) + adv1;
            e = (e > 0.f) ? e : 0.2f * e;
            float a = __expf(e);
            sl1 += a;
            int4 p = __ldg(row + o1);
            float2 f0 = __half22float2(*(__half2*)&p.x);
            float2 f1 = __half22float2(*(__half2*)&p.y);
            float2 f2 = __half22float2(*(__half2*)&p.z);
            float2 f3 = __half22float2(*(__half2*)&p.w);
            acc1[0] += a * f0.x; acc1[1] += a * f0.y;
            acc1[2] += a * f1.x; acc1[3] += a * f1.y;
            acc1[4] += a * f2.x; acc1[5] += a * f2.y;
            acc1[6] += a * f3.x; acc1[7] += a * f3.y;
        }
    }

    {
        float inv = 1.f / (sl0 + 1e-16f);
        __half2 hh[4];
#pragma unroll
        for (int k = 0; k < 4; k++) {
            float va = acc0[2 * k] * inv + bias[o0 * 8 + 2 * k];
            float vb = acc0[2 * k + 1] * inv + bias[o0 * 8 + 2 * k + 1];
            va = (va > 0.f) ? va : (__expf(va) - 1.f);
            vb = (vb > 0.f) ? vb : (__expf(vb) - 1.f);
            hh[k] = __floats2half2_rn(va, vb);
        }
        int4 st;
        st.x = *(int*)&hh[0]; st.y = *(int*)&hh[1];
        st.z = *(int*)&hh[2]; st.w = *(int*)&hh[3];
        *(int4*)(out + (size_t)w * F + o0 * 8) = st;
    }
    if (v1) {
        float inv = 1.f / (sl1 + 1e-16f);
        __half2 hh[4];
#pragma unroll
        for (int k = 0; k < 4; k++) {
            float va = acc1[2 * k] * inv + bias[o1 * 8 + 2 * k];
            float vb = acc1[2 * k + 1] * inv + bias[o1 * 8 + 2 * k + 1];
            va = (va > 0.f) ? va : (__expf(va) - 1.f);
            vb = (vb > 0.f) ? vb : (__expf(vb) - 1.f);
            hh[k] = __floats2half2_rn(va, vb);
        }
        int4 st;
        st.x = *(int*)&hh[0]; st.y = *(int*)&hh[1];
        st.z = *(int*)&hh[2]; st.w = *(int*)&hh[3];
        *(int4*)(out + (size_t)w * F + o1 * 8) = st;
    }
}

// ---------------- layer-2 aggregation + finalize (R7 direct-loop form) ---------
__global__ void gat_aggr2fin_k(const int4* __restrict__ hp16,
                               const float* __restrict__ as_,
                               const float* __restrict__ ad_,
                               const float* __restrict__ b2,
                               float* __restrict__ logits) {
    const int C = CLS, NO8 = L2F / 8;
    __shared__ float sh[8][L2F];
    int w = (blockIdx.x * blockDim.x + threadIdx.x) >> 5;
    int wl = threadIdx.x >> 5;
    int lane = threadIdx.x & 31;
    if (w >= NN) return;
    int r0 = g_rowptr[w], r1 = g_rowptr[w + 1];

    const int o0 = lane;
    const bool v0 = o0 < NO8;
    const int h0 = v0 ? (o0 * 8) / C : 0;
    const float adv0 = v0 ? ad_[w * HEADS + h0] : 0.f;

    float acc0[8] = {};
    float sl0 = 0.f;

#pragma unroll 4
    for (int j = r0; j < r1; j++) {
        int s = __ldg(&g_csrc[j]);
        if (v0) {
            float e = __ldg(&as_[s * HEADS + h0]) + adv0;
            e = (e > 0.f) ? e : 0.2f * e;
            float a = __expf(e);
            sl0 += a;
            int4 p = __ldg(hp16 + (size_t)s * NO8 + o0);
            float2 f0 = __half22float2(*(__half2*)&p.x);
            float2 f1 = __half22float2(*(__half2*)&p.y);
            float2 f2 = __half22float2(*(__half2*)&p.z);
            float2 f3 = __half22float2(*(__half2*)&p.w);
            acc0[0] += a * f0.x; acc0[1] += a * f0.y;
            acc0[2] += a * f1.x; acc0[3] += a * f1.y;
            acc0[4] += a * f2.x; acc0[5] += a * f2.y;
            acc0[6] += a * f3.x; acc0[7] += a * f3.y;
        }
    }

    if (v0) {
        float inv = 1.f / (sl0 + 1e-16f);
#pragma unroll
        for (int k = 0; k < 8; k++) sh[wl][o0 * 8 + k] = acc0[k] * inv;
    }
    __syncwarp();

    int c0 = lane, c1 = lane + 32;
    bool has1 = (c1 < CLS);
    float a0 = 0.f, a1 = 0.f;
#pragma unroll
    for (int h = 0; h < HEADS; h++) a0 += sh[wl][h * CLS + c0];
    float v0f = a0 * (1.f / HEADS) + b2[c0];
    float v1f = 0.f;
    if (has1) {
#pragma unroll
        for (int h = 0; h < HEADS; h++) a1 += sh[wl][h * CLS + c1];
        v1f = a1 * (1.f / HEADS) + b2[c1];
    }
    float mx = has1 ? fmaxf(v0f, v1f) : v0f;
#pragma unroll
    for (int o = 16; o; o >>= 1) mx = fmaxf(mx, __shfl_xor_sync(0xFFFFFFFFu, mx, o));
    float se = __expf(v0f - mx) + (has1 ? __expf(v1f - mx) : 0.f);
#pragma unroll
    for (int o = 16; o; o >>= 1) se += __shfl_xor_sync(0xFFFFFFFFu, se, o);
    float lse = logf(se) + mx;
    logits[(size_t)w * CLS + c0] = v0f - lse;
    if (has1) logits[(size_t)w * CLS + c1] = v1f - lse;
}

// ---------------- host ----------------------------------------------------------
#define HSMEM_NT64 ((2 * 128 * 40 + 2 * 64 * 40) * 2)
#define HSMEM_NT40 ((2 * 128 * 40 + 2 * 40 * 40) * 2)

extern "C" void kernel_launch(void* const* d_in, const int* in_sizes, int n_in,
                              void* d_out, int out_size) {
    const float* x     = (const float*)d_in[0];
    const void*  ei    = d_in[1];
    const float* emb_W = (const float*)d_in[2];
    const float* emb_b = (const float*)d_in[3];
    const float* W1    = (const float*)d_in[4];
    const float* at_s1 = (const float*)d_in[5];
    const float* at_d1 = (const float*)d_in[6];
    const float* b1    = (const float*)d_in[7];
    const float* W2    = (const float*)d_in[8];
    const float* at_s2 = (const float*)d_in[9];
    const float* at_d2 = (const float*)d_in[10];
    const float* b2    = (const float*)d_in[11];

    float* outp   = (float*)d_out;
    float* emb    = outp;
    float* logits = outp + (size_t)NN * HID;

    float *as1, *ad1, *as2, *ad2;
    __half *embh, *o1h, *w1t, *w2t, *xh, *xl, *w0h, *w0l;
    int4* hp16;
    cudaGetSymbolAddress((void**)&as1,  g_as1);
    cudaGetSymbolAddress((void**)&ad1,  g_ad1);
    cudaGetSymbolAddress((void**)&as2,  g_as2);
    cudaGetSymbolAddress((void**)&ad2,  g_ad2);
    cudaGetSymbolAddress((void**)&embh, g_embh);
    cudaGetSymbolAddress((void**)&o1h,  g_o1h);
    cudaGetSymbolAddress((void**)&w1t,  g_w1t);
    cudaGetSymbolAddress((void**)&w2t,  g_w2t);
    cudaGetSymbolAddress((void**)&xh,   g_xh);
    cudaGetSymbolAddress((void**)&xl,   g_xl);
    cudaGetSymbolAddress((void**)&w0h,  g_w0h);
    cudaGetSymbolAddress((void**)&w0l,  g_w0l);
    cudaGetSymbolAddress((void**)&hp16, g_hp16);

    cudaFuncSetAttribute(emb_gemm_k, cudaFuncAttributeMaxDynamicSharedMemorySize, EMB_SMEM);
    cudaFuncSetAttribute(hgemm_k<64, 2>, cudaFuncAttributeMaxDynamicSharedMemorySize, HSMEM_NT64);
    cudaFuncSetAttribute(hgemm_k<40, 1>, cudaFuncAttributeMaxDynamicSharedMemorySize, HSMEM_NT40);

    const int T = 256;
    const int MB = (NN + 127) / 128;

    // 0: detect, 1: prep (conv+init), 2: emb GEMM, 3: hgemm1 (big kernels early
    // so the ncu sampled launch lands on one of them), then CSR chain.
    detect_dtype_k<<<1, 32>>>(ei);
    prep_k<<<(SEGT + T - 1) / T, T>>>(ei, W1, W2, emb_W, x);
    emb_gemm_k<<<dim3(1, MB), 256, EMB_SMEM>>>(
        xh, xl, w0h, w0l, emb, emb_b, (__half2*)embh, NN);
    hgemm_k<64, 2><<<dim3(HEADS, MB), 256, HSMEM_NT64>>>(
        embh, w1t, NN, HID, L1F, (__half2*)hp16, at_s1, at_d1, as1, ad1);

    hist_k<<<(ET + T - 1) / T, T>>>(ei);
    blockscan_k<<<NB, 256>>>();
    bscan2_k<<<1, 256>>>();
    addoff_k<<<(NN + T - 1) / T, T>>>();
    scatter_k<<<(ET + T - 1) / T, T>>>(ei);

    gat_aggr1_k<<<(NN * 32 + T - 1) / T, T>>>(hp16, as1, ad1, b1, o1h);

    hgemm_k<40, 1><<<dim3(HEADS, MB), 256, HSMEM_NT40>>>(
        o1h, w2t, NN, L1F, L2F, (__half2*)hp16, at_s2, at_d2, as2, ad2);

    gat_aggr2fin_k<<<(NN * 32 + T - 1) / T, T>>>(hp16, as2, ad2, b2, logits);
}

// round 10
// speedup vs baseline: 1.0207x; 1.0069x over previous
#include <cuda_runtime.h>
#include <cuda_fp16.h>
#include <cstdint>
#include <cstddef>

#define NN    50000
#define EE    800000
#define ET    (EE + NN)
#define INC   128
#define HID   64
#define HEADS 5
#define CLS   40
#define L1F   (HEADS * HID)   // 320
#define L2F   (HEADS * CLS)   // 200
#define NB    ((NN + 255) / 256)
#define W1R   (HID + 8)       // 72 rows per head in w1t (64 data + 4 att + 4 pad)
#define W2R   (CLS + 8)       // 48 rows per head in w2t

// ---------------- scratch ----------------------------------------------------
__device__ __half g_xh  [(size_t)NN * INC];
__device__ __half g_xl  [(size_t)NN * INC];
__device__ __half g_w0h [HID * INC];
__device__ __half g_w0l [HID * INC];
__device__ __half g_embh[(size_t)NN * HID];
__device__ __half g_o1h [(size_t)NN * L1F];
__device__ int4   g_hp16[(size_t)NN * L1F / 8];
__device__ __half g_w1t [HEADS * W1R * HID];    // per head: 64 data rows + vs_h,vs_l,vd_h,vd_l + 4 zero
__device__ __half g_w2t [HEADS * W2R * L1F];    // per head: 40 data rows + 4 att rows + 4 zero
__device__ float  g_as1[NN * HEADS];
__device__ float  g_ad1[NN * HEADS];
__device__ float  g_as2[NN * HEADS];
__device__ float  g_ad2[NN * HEADS];
__device__ int    g_csrc[ET];
__device__ int    g_rowptr[NN + 1];
__device__ int    g_cnt[NN];
__device__ int    g_off[NN];
__device__ int    g_bsum[NB];
__device__ int    g_boff[NB];
__device__ int    g_is64;

// ---------------- dtype detect ------------------------------------------------
__global__ void detect_dtype_k(const void* ei) {
    const int* p = (const int*)ei;
    int t = threadIdx.x;
    int nz = 0;
    for (int i = t; i < 1024; i += 32)
        if (p[2 * i + 1] != 0) nz = 1;
    unsigned m = __ballot_sync(0xFFFFFFFFu, nz);
    if (t == 0) g_is64 = (m == 0) ? 1 : 0;
}

__device__ __forceinline__ void edge_at(const void* ei, int i, int& s, int& d) {
    if (i < EE) {
        if (g_is64) {
            const long long* p = (const long long*)ei;
            s = (int)p[i];
            d = (int)p[EE + i];
        } else {
            const int* p = (const int*)ei;
            s = p[i];
            d = p[EE + i];
        }
    } else {
        s = i - EE;
        d = i - EE;
    }
}

// ---------------- prep: weight/att conversion + init --------------------------
#define S0 (HEADS * HID * HID)          // w1t data         20480
#define S1 (S0 + HEADS * HID * 2)       // w1t att rows     +640
#define S2 (S1 + HEADS * 4 * HID)       // w1t zero rows    +1280
#define S3 (S2 + HEADS * CLS * L1F)     // w2t data         +64000
#define S4 (S3 + HEADS * L1F * 2)       // w2t att rows     +3200
#define S5 (S4 + HEADS * 4 * L1F)       // w2t zero rows    +6400
#define S6 (S5 + HID * INC)             // w0 split         +8192
#define S7 (S6 + NN * INC)              // x split          +6.4M
#define SEGT S7

__global__ void prep_k(const float* __restrict__ W1, const float* __restrict__ W2,
                       const float* __restrict__ W0, const float* __restrict__ x,
                       const float* __restrict__ as1, const float* __restrict__ ad1,
                       const float* __restrict__ as2, const float* __restrict__ ad2) {
    int i = blockIdx.x * blockDim.x + threadIdx.x;
    if (i < S0) {                       // w1t data: [h][n][k] = W1[k][h*64+n]
        int h = i / (HID * HID), rem = i % (HID * HID);
        int n = rem / HID, k = rem % HID;
        g_w1t[(h * W1R + n) * HID + k] = __float2half(W1[(size_t)k * L1F + h * HID + n]);
    } else if (i < S1) {                // w1t att rows: v[k] = sum_n W1[k][h*64+n]*att[h][n]
        int j = i - S0;
        int h = j / (HID * 2), rem = j % (HID * 2);
        int which = rem / HID, k = rem % HID;
        const float* att = which ? ad1 : as1;
        float v = 0.f;
        for (int n = 0; n < HID; n++)
            v += W1[(size_t)k * L1F + h * HID + n] * att[h * HID + n];
        __half hi = __float2half_rn(v);
        __half lo = __float2half_rn(v - __half2float(hi));
        g_w1t[(h * W1R + HID + which * 2 + 0) * HID + k] = hi;
        g_w1t[(h * W1R + HID + which * 2 + 1) * HID + k] = lo;
    } else if (i < S2) {                // w1t pad rows (unused cols NT+4..NT+7)
        int j = i - S1;
        int h = j / (4 * HID), rem = j % (4 * HID);
        int r = rem / HID, k = rem % HID;
        g_w1t[(h * W1R + HID + 4 + r) * HID + k] = __float2half(0.f);
    } else if (i < S3) {                // w2t data
        int j = i - S2;
        int h = j / (CLS * L1F), rem = j % (CLS * L1F);
        int n = rem / L1F, k = rem % L1F;
        g_w2t[(h * W2R + n) * L1F + k] = __float2half(W2[(size_t)k * L2F + h * CLS + n]);
    } else if (i < S4) {                // w2t att rows
        int j = i - S3;
        int h = j / (L1F * 2), rem = j % (L1F * 2);
        int which = rem / L1F, k = rem % L1F;
        const float* att = which ? ad2 : as2;
        float v = 0.f;
        for (int n = 0; n < CLS; n++)
            v += W2[(size_t)k * L2F + h * CLS + n] * att[h * CLS + n];
        __half hi = __float2half_rn(v);
        __half lo = __float2half_rn(v - __half2float(hi));
        g_w2t[(h * W2R + CLS + which * 2 + 0) * L1F + k] = hi;
        g_w2t[(h * W2R + CLS + which * 2 + 1) * L1F + k] = lo;
    } else if (i < S5) {                // w2t pad rows
        int j = i - S4;
        int h = j / (4 * L1F), rem = j % (4 * L1F);
        int r = rem / L1F, k = rem % L1F;
        g_w2t[(h * W2R + CLS + 4 + r) * L1F + k] = __float2half(0.f);
    } else if (i < S6) {                // w0 split (transposed)
        int j = i - S5;
        int n = j / INC, k = j % INC;
        float f = W0[(size_t)k * HID + n];
        __half h = __float2half_rn(f);
        g_w0h[j] = h;
        g_w0l[j] = __float2half_rn(f - __half2float(h));
    } else if (i < S7) {                // x split
        int j = i - S6;
        float f = x[j];
        __half h = __float2half_rn(f);
        g_xh[j] = h;
        g_xl[j] = __float2half_rn(f - __half2float(h));
    }
    if (i < NN) {
        g_cnt[i] = 0;
        g_off[i] = 0;
    }
}

__global__ void hist_k(const void* ei) {
    int i = blockIdx.x * blockDim.x + threadIdx.x;
    if (i >= ET) return;
    int s, d;
    edge_at(ei, i, s, d);
    atomicAdd(&g_cnt[d], 1);
}

// ---------------- parallel scan ------------------------------------------------
__global__ void blockscan_k() {
    __shared__ int sh[256];
    int b = blockIdx.x, t = threadIdx.x, i = b * 256 + t;
    int v = (i < NN) ? g_cnt[i] : 0;
    sh[t] = v;
    __syncthreads();
#pragma unroll
    for (int o = 1; o < 256; o <<= 1) {
        int u = (t >= o) ? sh[t - o] : 0;
        __syncthreads();
        sh[t] += u;
        __syncthreads();
    }
    if (i < NN) g_rowptr[i] = sh[t] - v;
    if (t == 255) g_bsum[b] = sh[255];
}

__global__ void bscan2_k() {
    __shared__ int sh[256];
    int t = threadIdx.x;
    int v = (t < NB) ? g_bsum[t] : 0;
    sh[t] = v;
    __syncthreads();
#pragma unroll
    for (int o = 1; o < 256; o <<= 1) {
        int u = (t >= o) ? sh[t - o] : 0;
        __syncthreads();
        sh[t] += u;
        __syncthreads();
    }
    if (t < NB) g_boff[t] = sh[t] - v;
}

__global__ void addoff_k() {
    int i = blockIdx.x * blockDim.x + threadIdx.x;
    if (i < NN) g_rowptr[i] += g_boff[i >> 8];
    if (i == 0) g_rowptr[NN] = ET;
}

__global__ void scatter_k(const void* ei) {
    int i = blockIdx.x * blockDim.x + threadIdx.x;
    if (i >= ET) return;
    int s, d;
    edge_at(ei, i, s, d);
    int pos = g_rowptr[d] + atomicAdd(&g_off[d], 1);
    g_csrc[pos] = s;
}

// ---------------- cp.async helpers --------------------------------------------
__device__ __forceinline__ void cp16h(__half* dst, const __half* src, bool pred) {
    uint32_t s = (uint32_t)__cvta_generic_to_shared(dst);
    int bytes = pred ? 16 : 0;
    asm volatile("cp.async.ca.shared.global [%0], [%1], 16, %2;\n"
                 :: "r"(s), "l"(src), "r"(bytes));
}
#define CP_COMMIT() asm volatile("cp.async.commit_group;\n" ::: "memory")
#define CP_WAIT(n)  asm volatile("cp.async.wait_group %0;\n" :: "n"(n) : "memory")

#define MMA16(cc, a, b)                                                         \
    asm volatile(                                                               \
        "mma.sync.aligned.m16n8k16.row.col.f32.f16.f16.f32 "                    \
        "{%0,%1,%2,%3},{%4,%5,%6,%7},{%8,%9},{%0,%1,%2,%3};\n"                  \
        : "+f"(cc[0]), "+f"(cc[1]), "+f"(cc[2]), "+f"(cc[3])                    \
        : "r"(a[0]), "r"(a[1]), "r"(a[2]), "r"(a[3]), "r"(b[0]), "r"(b[1]))

// ---------------- emb GEMM: fp16x3 --------------------------------------------
#define APL (128 * 40)
#define BPL (64 * 40)
#define STG (2 * APL + 2 * BPL)
#define EMB_SMEM (2 * STG * 2)

__global__ __launch_bounds__(256, 2)
void emb_gemm_k(const __half* __restrict__ Ah, const __half* __restrict__ Al,
                const __half* __restrict__ Bh, const __half* __restrict__ Bl,
                float* __restrict__ C, const float* __restrict__ bias,
                __half2* __restrict__ Ch, int M) {
    const int K = INC, Nc = HID;
    extern __shared__ __half smh[];
    int tid = threadIdx.x;
    int wid = tid >> 5, lane = tid & 31;
    int wm = wid & 3, wn = wid >> 2;
    int grp = lane >> 2, qid = lane & 3;
    int bm = blockIdx.y * 128;

    auto ldt = [&](int st, int k0) {
        __half* base = smh + st * STG;
        __half* Ahs = base;
        __half* Als = base + APL;
        __half* Bhs = base + 2 * APL;
        __half* Bls = base + 2 * APL + BPL;
#pragma unroll
        for (int t = 0; t < 2; t++) {
            int idx = tid + t * 256;
            int row = idx >> 2, c4 = idx & 3;
            int gm = bm + row;
            cp16h(Ahs + row * 40 + c4 * 8, Ah + (size_t)gm * K + k0 + c4 * 8, gm < M);
            cp16h(Als + row * 40 + c4 * 8, Al + (size_t)gm * K + k0 + c4 * 8, gm < M);
        }
        {
            int n = tid >> 2, c4 = tid & 3;
            cp16h(Bhs + n * 40 + c4 * 8, Bh + (size_t)n * K + k0 + c4 * 8, true);
            cp16h(Bls + n * 40 + c4 * 8, Bl + (size_t)n * K + k0 + c4 * 8, true);
        }
    };

    float c[2][4][4] = {};
    const int nk = K >> 5;
    ldt(0, 0);
    CP_COMMIT();

    for (int t = 0; t < nk; t++) {
        if (t + 1 < nk) {
            ldt((t + 1) & 1, (t + 1) << 5);
            CP_COMMIT();
            CP_WAIT(1);
        } else {
            CP_WAIT(0);
        }
        __syncthreads();
        const __half* base = smh + (t & 1) * STG;
        const __half* Ahs = base;
        const __half* Als = base + APL;
        const __half* Bhs = base + 2 * APL;
        const __half* Bls = base + 2 * APL + BPL;
#pragma unroll
        for (int kk = 0; kk < 32; kk += 16) {
            uint32_t ah[2][4], al[2][4], bh[4][2], bl[4][2];
#pragma unroll
            for (int mi = 0; mi < 2; mi++) {
                int r = wm * 32 + mi * 16 + grp;
                ah[mi][0] = *(const uint32_t*)&Ahs[r * 40 + kk + 2 * qid];
                ah[mi][1] = *(const uint32_t*)&Ahs[(r + 8) * 40 + kk + 2 * qid];
                ah[mi][2] = *(const uint32_t*)&Ahs[r * 40 + kk + 2 * qid + 8];
                ah[mi][3] = *(const uint32_t*)&Ahs[(r + 8) * 40 + kk + 2 * qid + 8];
                al[mi][0] = *(const uint32_t*)&Als[r * 40 + kk + 2 * qid];
                al[mi][1] = *(const uint32_t*)&Als[(r + 8) * 40 + kk + 2 * qid];
                al[mi][2] = *(const uint32_t*)&Als[r * 40 + kk + 2 * qid + 8];
                al[mi][3] = *(const uint32_t*)&Als[(r + 8) * 40 + kk + 2 * qid + 8];
            }
#pragma unroll
            for (int ni = 0; ni < 4; ni++) {
                int cn = wn * 32 + ni * 8 + grp;
                bh[ni][0] = *(const uint32_t*)&Bhs[cn * 40 + kk + 2 * qid];
                bh[ni][1] = *(const uint32_t*)&Bhs[cn * 40 + kk + 2 * qid + 8];
                bl[ni][0] = *(const uint32_t*)&Bls[cn * 40 + kk + 2 * qid];
                bl[ni][1] = *(const uint32_t*)&Bls[cn * 40 + kk + 2 * qid + 8];
            }
#pragma unroll
            for (int mi = 0; mi < 2; mi++)
#pragma unroll
                for (int ni = 0; ni < 4; ni++) {
                    MMA16(c[mi][ni], ah[mi], bh[ni]);
                    MMA16(c[mi][ni], ah[mi], bl[ni]);
                    MMA16(c[mi][ni], al[mi], bh[ni]);
                }
        }
        __syncthreads();
    }

#pragma unroll
    for (int mi = 0; mi < 2; mi++) {
#pragma unroll
        for (int ni = 0; ni < 4; ni++) {
            int row = bm + wm * 32 + mi * 16 + grp;
            int col = wn * 32 + ni * 8 + 2 * qid;
            float bx = bias[col], by = bias[col + 1];
            float v0 = c[mi][ni][0] + bx, v1 = c[mi][ni][1] + by;
            float v2 = c[mi][ni][2] + bx, v3 = c[mi][ni][3] + by;
            if (row < M) {
                *(float2*)&C[(size_t)row * Nc + col] = make_float2(v0, v1);
                Ch[((size_t)row * Nc + col) / 2] = __floats2half2_rn(v0, v1);
            }
            if (row + 8 < M) {
                *(float2*)&C[(size_t)(row + 8) * Nc + col] = make_float2(v2, v3);
                Ch[((size_t)(row + 8) * Nc + col) / 2] = __floats2half2_rn(v2, v3);
            }
        }
    }
}

// ---------------- fp16 GAT GEMM with in-MMA attention dots --------------------
// B has NT data cols + 4 att cols (vs_h, vs_l, vd_h, vd_l) + 4 pad.
// WM=8, WN=1: warp owns 16 rows x (NT+8) cols.  grid = (HEADS, MB).
// Epilogue: data cols -> fp16 hp; att col group -> plain stores of dots.
template <int NT, int KC>
__global__ __launch_bounds__(256, 3)
void hgemm_k(const __half* __restrict__ A, const __half* __restrict__ Bt,
             int M,
             __half2* __restrict__ hp16,
             float* __restrict__ as_, float* __restrict__ ad_) {
    constexpr int K = KC;
    constexpr int NTE = NT + 8;
    constexpr int NI = NTE / 8;
    constexpr int AST = 128 * 40;
    constexpr int BST = NTE * 40;
    constexpr int NB4 = NTE * 4;

    extern __shared__ __half smh[];
    __half* Asm = smh;
    __half* Bsm = smh + 2 * AST;
    int tid = threadIdx.x;
    int wid = tid >> 5, lane = tid & 31;
    int grp = lane >> 2, qid = lane & 3;
    int bm = blockIdx.y * 128;
    int hidx = blockIdx.x;
    const __half* Bth = Bt + (size_t)hidx * NTE * K;

    auto ldt = [&](int b, int k0) {
        __half* Ab = Asm + b * AST;
        __half* Bb = Bsm + b * BST;
#pragma unroll
        for (int t = 0; t < 2; t++) {
            int idx = tid + t * 256;
            int row = idx >> 2, c4 = idx & 3;
            int gm = bm + row;
            cp16h(Ab + row * 40 + c4 * 8, A + (size_t)gm * K + k0 + c4 * 8, gm < M);
        }
#pragma unroll
        for (int t = 0; t < (NB4 + 255) / 256; t++) {
            int idx = tid + t * 256;
            if (idx < NB4) {
                int n = idx >> 2, c4 = idx & 3;
                cp16h(Bb + n * 40 + c4 * 8, Bth + (size_t)n * K + k0 + c4 * 8, true);
            }
        }
    };

    float c[NI][4] = {};
    constexpr int nk = K >> 5;
    ldt(0, 0);
    CP_COMMIT();

    for (int t = 0; t < nk; t++) {
        if (t + 1 < nk) {
            ldt((t + 1) & 1, (t + 1) << 5);
            CP_COMMIT();
            CP_WAIT(1);
        } else {
            CP_WAIT(0);
        }
        __syncthreads();
        const __half* Ab = Asm + (t & 1) * AST;
        const __half* Bb = Bsm + (t & 1) * BST;
#pragma unroll
        for (int kk = 0; kk < 32; kk += 16) {
            uint32_t a[4], b[NI][2];
            int r = wid * 16 + grp;
            a[0] = *(const uint32_t*)&Ab[r * 40 + kk + 2 * qid];
            a[1] = *(const uint32_t*)&Ab[(r + 8) * 40 + kk + 2 * qid];
            a[2] = *(const uint32_t*)&Ab[r * 40 + kk + 2 * qid + 8];
            a[3] = *(const uint32_t*)&Ab[(r + 8) * 40 + kk + 2 * qid + 8];
#pragma unroll
            for (int ni = 0; ni < NI; ni++) {
                int cn = ni * 8 + grp;
                b[ni][0] = *(const uint32_t*)&Bb[cn * 40 + kk + 2 * qid];
                b[ni][1] = *(const uint32_t*)&Bb[cn * 40 + kk + 2 * qid + 8];
            }
#pragma unroll
            for (int ni = 0; ni < NI; ni++)
                MMA16(c[ni], a, b[ni]);
        }
        __syncthreads();
    }

    // epilogue
    int gr0 = bm + wid * 16 + grp;
    int gr1 = gr0 + 8;
    int bn = hidx * NT;
#pragma unroll
    for (int ni = 0; ni < NI - 1; ni++) {     // data columns
        int col = bn + ni * 8 + 2 * qid;
        if (gr0 < M) hp16[((size_t)gr0 * (HEADS * NT) + col) / 2] = __floats2half2_rn(c[ni][0], c[ni][1]);
        if (gr1 < M) hp16[((size_t)gr1 * (HEADS * NT) + col) / 2] = __floats2half2_rn(c[ni][2], c[ni][3]);
    }
    {   // att column group: qid0 -> as, qid1 -> ad
        float u0 = c[NI - 1][0] + c[NI - 1][1];
        float u1 = c[NI - 1][2] + c[NI - 1][3];
        if (qid == 0) {
            if (gr0 < M) as_[(size_t)gr0 * HEADS + hidx] = u0;
            if (gr1 < M) as_[(size_t)gr1 * HEADS + hidx] = u1;
        } else if (qid == 1) {
            if (gr0 < M) ad_[(size_t)gr0 * HEADS + hidx] = u0;
            if (gr1 < M) ad_[(size_t)gr1 * HEADS + hidx] = u1;
        }
    }
}

// ---------------- layer-1 aggregation (direct loop) ---------------------------
__global__ void gat_aggr1_k(const int4* __restrict__ hp16,
                            const float* __restrict__ as_,
                            const float* __restrict__ ad_,
                            const float* __restrict__ bias,
                            __half* __restrict__ out) {
    const int C = HID, F = L1F, NO8 = F / 8;
    int w = (blockIdx.x * blockDim.x + threadIdx.x) >> 5;
    int lane = threadIdx.x & 31;
    if (w >= NN) return;
    int r0 = g_rowptr[w], r1 = g_rowptr[w + 1];

    const int o0 = lane, o1 = lane + 32;
    const bool v1 = o1 < NO8;
    const int h0 = (o0 * 8) / C;
    const int h1 = v1 ? (o1 * 8) / C : 0;
    const float adv0 = ad_[w * HEADS + h0];
    const float adv1 = v1 ? ad_[w * HEADS + h1] : 0.f;

    float acc0[8] = {}, acc1[8] = {};
    float sl0 = 0.f, sl1 = 0.f;

#pragma unroll 4
    for (int j = r0; j < r1; j++) {
        int s = __ldg(&g_csrc[j]);
        const int4* row = hp16 + (size_t)s * NO8;
        {
            float e = __ldg(&as_[s * HEADS + h0]) + adv0;
            e = (e > 0.f) ? e : 0.2f * e;
            float a = __expf(e);
            sl0 += a;
            int4 p = __ldg(row + o0);
            float2 f0 = __half22float2(*(__half2*)&p.x);
            float2 f1 = __half22float2(*(__half2*)&p.y);
            float2 f2 = __half22float2(*(__half2*)&p.z);
            float2 f3 = __half22float2(*(__half2*)&p.w);
            acc0[0] += a * f0.x; acc0[1] += a * f0.y;
            acc0[2] += a * f1.x; acc0[3] += a * f1.y;
            acc0[4] += a * f2.x; acc0[5] += a * f2.y;
            acc0[6] += a * f3.x; acc0[7] += a * f3.y;
        }
        if (v1) {
            float e = __ldg(&as_[s * HEADS + h1]) + adv1;
            e = (e > 0.f) ? e : 0.2f * e;
            float a = __expf(e);
            sl1 += a;
            int4 p = __ldg(row + o1);
            float2 f0 = __half22float2(*(__half2*)&p.x);
            float2 f1 = __half22float2(*(__half2*)&p.y);
            float2 f2 = __half22float2(*(__half2*)&p.z);
            float2 f3 = __half22float2(*(__half2*)&p.w);
            acc1[0] += a * f0.x; acc1[1] += a * f0.y;
            acc1[2] += a * f1.x; acc1[3] += a * f1.y;
            acc1[4] += a * f2.x; acc1[5] += a * f2.y;
            acc1[6] += a * f3.x; acc1[7] += a * f3.y;
        }
    }

    {
        float inv = 1.f / (sl0 + 1e-16f);
        __half2 hh[4];
#pragma unroll
        for (int k = 0; k < 4; k++) {
            float va = acc0[2 * k] * inv + bias[o0 * 8 + 2 * k];
            float vb = acc0[2 * k + 1] * inv + bias[o0 * 8 + 2 * k + 1];
            va = (va > 0.f) ? va : (__expf(va) - 1.f);
            vb = (vb > 0.f) ? vb : (__expf(vb) - 1.f);
            hh[k] = __floats2half2_rn(va, vb);
        }
        int4 st;
        st.x = *(int*)&hh[0]; st.y = *(int*)&hh[1];
        st.z = *(int*)&hh[2]; st.w = *(int*)&hh[3];
        *(int4*)(out + (size_t)w * F + o0 * 8) = st;
    }
    if (v1) {
        float inv = 1.f / (sl1 + 1e-16f);
        __half2 hh[4];
#pragma unroll
        for (int k = 0; k < 4; k++) {
            float va = acc1[2 * k] * inv + bias[o1 * 8 + 2 * k];
            float vb = acc1[2 * k + 1] * inv + bias[o1 * 8 + 2 * k + 1];
            va = (va > 0.f) ? va : (__expf(va) - 1.f);
            vb = (vb > 0.f) ? vb : (__expf(vb) - 1.f);
            hh[k] = __floats2half2_rn(va, vb);
        }
        int4 st;
        st.x = *(int*)&hh[0]; st.y = *(int*)&hh[1];
        st.z = *(int*)&hh[2]; st.w = *(int*)&hh[3];
        *(int4*)(out + (size_t)w * F + o1 * 8) = st;
    }
}

// ---------------- layer-2 aggregation + finalize -------------------------------
__global__ void gat_aggr2fin_k(const int4* __restrict__ hp16,
                               const float* __restrict__ as_,
                               const float* __restrict__ ad_,
                               const float* __restrict__ b2,
                               float* __restrict__ logits) {
    const int C = CLS, NO8 = L2F / 8;
    __shared__ float sh[8][L2F];
    int w = (blockIdx.x * blockDim.x + threadIdx.x) >> 5;
    int wl = threadIdx.x >> 5;
    int lane = threadIdx.x & 31;
    if (w >= NN) return;
    int r0 = g_rowptr[w], r1 = g_rowptr[w + 1];

    const int o0 = lane;
    const bool v0 = o0 < NO8;
    const int h0 = v0 ? (o0 * 8) / C : 0;
    const float adv0 = v0 ? ad_[w * HEADS + h0] : 0.f;

    float acc0[8] = {};
    float sl0 = 0.f;

#pragma unroll 4
    for (int j = r0; j < r1; j++) {
        int s = __ldg(&g_csrc[j]);
        if (v0) {
            float e = __ldg(&as_[s * HEADS + h0]) + adv0;
            e = (e > 0.f) ? e : 0.2f * e;
            float a = __expf(e);
            sl0 += a;
            int4 p = __ldg(hp16 + (size_t)s * NO8 + o0);
            float2 f0 = __half22float2(*(__half2*)&p.x);
            float2 f1 = __half22float2(*(__half2*)&p.y);
            float2 f2 = __half22float2(*(__half2*)&p.z);
            float2 f3 = __half22float2(*(__half2*)&p.w);
            acc0[0] += a * f0.x; acc0[1] += a * f0.y;
            acc0[2] += a * f1.x; acc0[3] += a * f1.y;
            acc0[4] += a * f2.x; acc0[5] += a * f2.y;
            acc0[6] += a * f3.x; acc0[7] += a * f3.y;
        }
    }

    if (v0) {
        float inv = 1.f / (sl0 + 1e-16f);
#pragma unroll
        for (int k = 0; k < 8; k++) sh[wl][o0 * 8 + k] = acc0[k] * inv;
    }
    __syncwarp();

    int c0 = lane, c1 = lane + 32;
    bool has1 = (c1 < CLS);
    float a0 = 0.f, a1 = 0.f;
#pragma unroll
    for (int h = 0; h < HEADS; h++) a0 += sh[wl][h * CLS + c0];
    float v0f = a0 * (1.f / HEADS) + b2[c0];
    float v1f = 0.f;
    if (has1) {
#pragma unroll
        for (int h = 0; h < HEADS; h++) a1 += sh[wl][h * CLS + c1];
        v1f = a1 * (1.f / HEADS) + b2[c1];
    }
    float mx = has1 ? fmaxf(v0f, v1f) : v0f;
#pragma unroll
    for (int o = 16; o; o >>= 1) mx = fmaxf(mx, __shfl_xor_sync(0xFFFFFFFFu, mx, o));
    float se = __expf(v0f - mx) + (has1 ? __expf(v1f - mx) : 0.f);
#pragma unroll
    for (int o = 16; o; o >>= 1) se += __shfl_xor_sync(0xFFFFFFFFu, se, o);
    float lse = logf(se) + mx;
    logits[(size_t)w * CLS + c0] = v0f - lse;
    if (has1) logits[(size_t)w * CLS + c1] = v1f - lse;
}

// ---------------- host ----------------------------------------------------------
#define HSMEM_L1 ((2 * 128 * 40 + 2 * (HID + 8) * 40) * 2)
#define HSMEM_L2 ((2 * 128 * 40 + 2 * (CLS + 8) * 40) * 2)

extern "C" void kernel_launch(void* const* d_in, const int* in_sizes, int n_in,
                              void* d_out, int out_size) {
    const float* x     = (const float*)d_in[0];
    const void*  ei    = d_in[1];
    const float* emb_W = (const float*)d_in[2];
    const float* emb_b = (const float*)d_in[3];
    const float* W1    = (const float*)d_in[4];
    const float* at_s1 = (const float*)d_in[5];
    const float* at_d1 = (const float*)d_in[6];
    const float* b1    = (const float*)d_in[7];
    const float* W2    = (const float*)d_in[8];
    const float* at_s2 = (const float*)d_in[9];
    const float* at_d2 = (const float*)d_in[10];
    const float* b2    = (const float*)d_in[11];

    float* outp   = (float*)d_out;
    float* emb    = outp;
    float* logits = outp + (size_t)NN * HID;

    float *as1, *ad1, *as2, *ad2;
    __half *embh, *o1h, *w1t, *w2t, *xh, *xl, *w0h, *w0l;
    int4* hp16;
    cudaGetSymbolAddress((void**)&as1,  g_as1);
    cudaGetSymbolAddress((void**)&ad1,  g_ad1);
    cudaGetSymbolAddress((void**)&as2,  g_as2);
    cudaGetSymbolAddress((void**)&ad2,  g_ad2);
    cudaGetSymbolAddress((void**)&embh, g_embh);
    cudaGetSymbolAddress((void**)&o1h,  g_o1h);
    cudaGetSymbolAddress((void**)&w1t,  g_w1t);
    cudaGetSymbolAddress((void**)&w2t,  g_w2t);
    cudaGetSymbolAddress((void**)&xh,   g_xh);
    cudaGetSymbolAddress((void**)&xl,   g_xl);
    cudaGetSymbolAddress((void**)&w0h,  g_w0h);
    cudaGetSymbolAddress((void**)&w0l,  g_w0l);
    cudaGetSymbolAddress((void**)&hp16, g_hp16);

    cudaFuncSetAttribute(emb_gemm_k, cudaFuncAttributeMaxDynamicSharedMemorySize, EMB_SMEM);
    cudaFuncSetAttribute(hgemm_k<HID, HID>, cudaFuncAttributeMaxDynamicSharedMemorySize, HSMEM_L1);
    cudaFuncSetAttribute(hgemm_k<CLS, L1F>, cudaFuncAttributeMaxDynamicSharedMemorySize, HSMEM_L2);

    const int T = 256;
    const int MB = (NN + 127) / 128;

    // 0: detect, 1: prep, 2: emb GEMM, 3: hgemm1 (profiled), then CSR chain.
    detect_dtype_k<<<1, 32>>>(ei);
    prep_k<<<(SEGT + T - 1) / T, T>>>(W1, W2, emb_W, x, at_s1, at_d1, at_s2, at_d2);
    emb_gemm_k<<<dim3(1, MB), 256, EMB_SMEM>>>(
        xh, xl, w0h, w0l, emb, emb_b, (__half2*)embh, NN);
    hgemm_k<HID, HID><<<dim3(HEADS, MB), 256, HSMEM_L1>>>(
        embh, w1t, NN, (__half2*)hp16, as1, ad1);

    hist_k<<<(ET + T - 1) / T, T>>>(ei);
    blockscan_k<<<NB, 256>>>();
    bscan2_k<<<1, 256>>>();
    addoff_k<<<(NN + T - 1) / T, T>>>();
    scatter_k<<<(ET + T - 1) / T, T>>>(ei);

    gat_aggr1_k<<<(NN * 32 + T - 1) / T, T>>>(hp16, as1, ad1, b1, o1h);

    hgemm_k<CLS, L1F><<<dim3(HEADS, MB), 256, HSMEM_L2>>>(
        o1h, w2t, NN, (__half2*)hp16, as2, ad2);

    gat_aggr2fin_k<<<(NN * 32 + T - 1) / T, T>>>(hp16, as2, ad2, b2, logits);
}

// round 11
// speedup vs baseline: 1.2157x; 1.1910x over previous
#include <cuda_runtime.h>
#include <cuda_fp16.h>
#include <cstdint>
#include <cstddef>

#define NN    50000
#define EE    800000
#define ET    (EE + NN)
#define INC   128
#define HID   64
#define HEADS 5
#define CLS   40
#define L1F   (HEADS * HID)   // 320
#define L2F   (HEADS * CLS)   // 200
#define NB    ((NN + 255) / 256)
#define W1R   (HID + 8)
#define W2R   (CLS + 8)

// ---------------- scratch ----------------------------------------------------
__device__ __half g_embh[(size_t)NN * HID];
__device__ __half g_o1h [(size_t)NN * L1F];
__device__ int4   g_hp16[(size_t)NN * L1F / 8];
__device__ __half g_w1t [HEADS * W1R * HID];
__device__ __half g_w2t [HEADS * W2R * L1F];
__device__ float  g_as1[NN * HEADS];
__device__ float  g_ad1[NN * HEADS];
__device__ float  g_as2[NN * HEADS];
__device__ float  g_ad2[NN * HEADS];
__device__ int    g_csrc[ET];
__device__ int    g_rowptr[NN + 1];
__device__ int    g_cnt[NN];
__device__ int    g_off[NN];
__device__ int    g_bsum[NB];
__device__ int    g_boff[NB];
__device__ int    g_is64;

// ---------------- dtype detect ------------------------------------------------
__global__ void detect_dtype_k(const void* ei) {
    const int* p = (const int*)ei;
    int t = threadIdx.x;
    int nz = 0;
    for (int i = t; i < 1024; i += 32)
        if (p[2 * i + 1] != 0) nz = 1;
    unsigned m = __ballot_sync(0xFFFFFFFFu, nz);
    if (t == 0) g_is64 = (m == 0) ? 1 : 0;
}

__device__ __forceinline__ void edge_at(const void* ei, int i, int& s, int& d) {
    if (i < EE) {
        if (g_is64) {
            const long long* p = (const long long*)ei;
            s = (int)p[i];
            d = (int)p[EE + i];
        } else {
            const int* p = (const int*)ei;
            s = p[i];
            d = p[EE + i];
        }
    } else {
        s = i - EE;
        d = i - EE;
    }
}

// ---------------- prep: weight conversion + init (weights only, small) --------
#define S0 (HEADS * HID * HID)
#define S1 (S0 + HEADS * HID * 2)
#define S2 (S1 + HEADS * 4 * HID)
#define S3 (S2 + HEADS * CLS * L1F)
#define S4 (S3 + HEADS * L1F * 2)
#define S5 (S4 + HEADS * 4 * L1F)
#define SEGT S5

__global__ void prep_k(const float* __restrict__ W1, const float* __restrict__ W2,
                       const float* __restrict__ as1, const float* __restrict__ ad1,
                       const float* __restrict__ as2, const float* __restrict__ ad2) {
    int i = blockIdx.x * blockDim.x + threadIdx.x;
    if (i < S0) {
        int h = i / (HID * HID), rem = i % (HID * HID);
        int n = rem / HID, k = rem % HID;
        g_w1t[(h * W1R + n) * HID + k] = __float2half(W1[(size_t)k * L1F + h * HID + n]);
    } else if (i < S1) {
        int j = i - S0;
        int h = j / (HID * 2), rem = j % (HID * 2);
        int which = rem / HID, k = rem % HID;
        const float* att = which ? ad1 : as1;
        float v = 0.f;
        for (int n = 0; n < HID; n++)
            v += W1[(size_t)k * L1F + h * HID + n] * att[h * HID + n];
        __half hi = __float2half_rn(v);
        __half lo = __float2half_rn(v - __half2float(hi));
        g_w1t[(h * W1R + HID + which * 2 + 0) * HID + k] = hi;
        g_w1t[(h * W1R + HID + which * 2 + 1) * HID + k] = lo;
    } else if (i < S2) {
        int j = i - S1;
        int h = j / (4 * HID), rem = j % (4 * HID);
        int r = rem / HID, k = rem % HID;
        g_w1t[(h * W1R + HID + 4 + r) * HID + k] = __float2half(0.f);
    } else if (i < S3) {
        int j = i - S2;
        int h = j / (CLS * L1F), rem = j % (CLS * L1F);
        int n = rem / L1F, k = rem % L1F;
        g_w2t[(h * W2R + n) * L1F + k] = __float2half(W2[(size_t)k * L2F + h * CLS + n]);
    } else if (i < S4) {
        int j = i - S3;
        int h = j / (L1F * 2), rem = j % (L1F * 2);
        int which = rem / L1F, k = rem % L1F;
        const float* att = which ? ad2 : as2;
        float v = 0.f;
        for (int n = 0; n < CLS; n++)
            v += W2[(size_t)k * L2F + h * CLS + n] * att[h * CLS + n];
        __half hi = __float2half_rn(v);
        __half lo = __float2half_rn(v - __half2float(hi));
        g_w2t[(h * W2R + CLS + which * 2 + 0) * L1F + k] = hi;
        g_w2t[(h * W2R + CLS + which * 2 + 1) * L1F + k] = lo;
    } else if (i < S5) {
        int j = i - S4;
        int h = j / (4 * L1F), rem = j % (4 * L1F);
        int r = rem / L1F, k = rem % L1F;
        g_w2t[(h * W2R + CLS + 4 + r) * L1F + k] = __float2half(0.f);
    }
    if (i < NN) {
        g_cnt[i] = 0;
        g_off[i] = 0;
    }
}

__global__ void hist_k(const void* ei) {
    int i = blockIdx.x * blockDim.x + threadIdx.x;
    if (i >= ET) return;
    int s, d;
    edge_at(ei, i, s, d);
    atomicAdd(&g_cnt[d], 1);
}

// ---------------- parallel scan ------------------------------------------------
__global__ void blockscan_k() {
    __shared__ int sh[256];
    int b = blockIdx.x, t = threadIdx.x, i = b * 256 + t;
    int v = (i < NN) ? g_cnt[i] : 0;
    sh[t] = v;
    __syncthreads();
#pragma unroll
    for (int o = 1; o < 256; o <<= 1) {
        int u = (t >= o) ? sh[t - o] : 0;
        __syncthreads();
        sh[t] += u;
        __syncthreads();
    }
    if (i < NN) g_rowptr[i] = sh[t] - v;
    if (t == 255) g_bsum[b] = sh[255];
}

__global__ void bscan2_k() {
    __shared__ int sh[256];
    int t = threadIdx.x;
    int v = (t < NB) ? g_bsum[t] : 0;
    sh[t] = v;
    __syncthreads();
#pragma unroll
    for (int o = 1; o < 256; o <<= 1) {
        int u = (t >= o) ? sh[t - o] : 0;
        __syncthreads();
        sh[t] += u;
        __syncthreads();
    }
    if (t < NB) g_boff[t] = sh[t] - v;
}

__global__ void addoff_k() {
    int i = blockIdx.x * blockDim.x + threadIdx.x;
    if (i < NN) g_rowptr[i] += g_boff[i >> 8];
    if (i == 0) g_rowptr[NN] = ET;
}

__global__ void scatter_k(const void* ei) {
    int i = blockIdx.x * blockDim.x + threadIdx.x;
    if (i >= ET) return;
    int s, d;
    edge_at(ei, i, s, d);
    int pos = g_rowptr[d] + atomicAdd(&g_off[d], 1);
    g_csrc[pos] = s;
}

// ---------------- cp.async helpers --------------------------------------------
__device__ __forceinline__ void cp16(float* dst, const float* src, bool pred) {
    uint32_t s = (uint32_t)__cvta_generic_to_shared(dst);
    int bytes = pred ? 16 : 0;
    asm volatile("cp.async.ca.shared.global [%0], [%1], 16, %2;\n"
                 :: "r"(s), "l"(src), "r"(bytes));
}
__device__ __forceinline__ void cp16h(__half* dst, const __half* src, bool pred) {
    uint32_t s = (uint32_t)__cvta_generic_to_shared(dst);
    int bytes = pred ? 16 : 0;
    asm volatile("cp.async.ca.shared.global [%0], [%1], 16, %2;\n"
                 :: "r"(s), "l"(src), "r"(bytes));
}
#define CP_COMMIT() asm volatile("cp.async.commit_group;\n" ::: "memory")
#define CP_WAIT(n)  asm volatile("cp.async.wait_group %0;\n" :: "n"(n) : "memory")

__device__ __forceinline__ void tf_split(float f, uint32_t& hi, uint32_t& lo) {
    uint32_t u = __float_as_uint(f);
    hi = u & 0xFFFFE000u;
    float r = f - __uint_as_float(hi);
    lo = __float_as_uint(r) & 0xFFFFE000u;
}

#define MMA8(cc, a, b)                                                          \
    asm volatile(                                                               \
        "mma.sync.aligned.m16n8k8.row.col.f32.tf32.tf32.f32 "                   \
        "{%0,%1,%2,%3},{%4,%5,%6,%7},{%8,%9},{%0,%1,%2,%3};\n"                  \
        : "+f"(cc[0]), "+f"(cc[1]), "+f"(cc[2]), "+f"(cc[3])                    \
        : "r"(a[0]), "r"(a[1]), "r"(a[2]), "r"(a[3]), "r"(b[0]), "r"(b[1]))

#define MMA16(cc, a, b)                                                         \
    asm volatile(                                                               \
        "mma.sync.aligned.m16n8k16.row.col.f32.f16.f16.f32 "                    \
        "{%0,%1,%2,%3},{%4,%5,%6,%7},{%8,%9},{%0,%1,%2,%3};\n"                  \
        : "+f"(cc[0]), "+f"(cc[1]), "+f"(cc[2]), "+f"(cc[3])                    \
        : "r"(a[0]), "r"(a[1]), "r"(a[2]), "r"(a[3]), "r"(b[0]), "r"(b[1]))

// ---------------- TF32x3 GEMM (emb layer: fp32 out + bias + fp16 copy) ---------
#define GEMM_SMEM_BYTES ((2 * 128 * 40 + 2 * 32 * 72) * 4)

__global__ __launch_bounds__(256, 2)
void tf32_gemm_k(const float* __restrict__ A, const float* __restrict__ B,
                 float* __restrict__ C, const float* __restrict__ bias,
                 __half2* __restrict__ Ch, int M, int K, int Nc) {
    extern __shared__ float sm[];
    float* Asm = sm;
    float* Bsm = sm + 2 * 128 * 40;
    int tid = threadIdx.x;
    int wid = tid >> 5, lane = tid & 31;
    int wm = wid & 3, wn = wid >> 2;
    int grp = lane >> 2, qid = lane & 3;
    int bm = blockIdx.y * 128, bn = blockIdx.x * 64;

    auto ldt = [&](int b, int k0) {
        float* Ab = Asm + b * 5120;
        float* Bb = Bsm + b * 2304;
#pragma unroll
        for (int t = 0; t < 4; t++) {
            int idx = tid + t * 256;
            int row = idx >> 3, c4 = idx & 7;
            int gm = bm + row;
            cp16(Ab + row * 40 + c4 * 4, A + (size_t)gm * K + k0 + c4 * 4, gm < M);
        }
#pragma unroll
        for (int t = 0; t < 2; t++) {
            int idx = tid + t * 256;
            int kk = idx >> 4, n4 = idx & 15;
            int gn = bn + n4 * 4;
            cp16(Bb + kk * 72 + n4 * 4, B + (size_t)(k0 + kk) * Nc + gn, gn < Nc);
        }
    };

    float c[2][4][4] = {};
    int nk = K >> 5;
    ldt(0, 0);
    CP_COMMIT();

    for (int t = 0; t < nk; t++) {
        if (t + 1 < nk) {
            ldt((t + 1) & 1, (t + 1) << 5);
            CP_COMMIT();
            CP_WAIT(1);
        } else {
            CP_WAIT(0);
        }
        __syncthreads();
        const float* Ab = Asm + (t & 1) * 5120;
        const float* Bb = Bsm + (t & 1) * 2304;
#pragma unroll
        for (int kk = 0; kk < 32; kk += 8) {
            uint32_t ah[2][4], al[2][4], bh[4][2], bl[4][2];
#pragma unroll
            for (int mi = 0; mi < 2; mi++) {
                int r = wm * 32 + mi * 16 + grp;
                tf_split(Ab[r * 40 + kk + qid],           ah[mi][0], al[mi][0]);
                tf_split(Ab[(r + 8) * 40 + kk + qid],     ah[mi][1], al[mi][1]);
                tf_split(Ab[r * 40 + kk + qid + 4],       ah[mi][2], al[mi][2]);
                tf_split(Ab[(r + 8) * 40 + kk + qid + 4], ah[mi][3], al[mi][3]);
            }
#pragma unroll
            for (int ni = 0; ni < 4; ni++) {
                int cn = wn * 32 + ni * 8 + grp;
                tf_split(Bb[(kk + qid) * 72 + cn],     bh[ni][0], bl[ni][0]);
                tf_split(Bb[(kk + qid + 4) * 72 + cn], bh[ni][1], bl[ni][1]);
            }
#pragma unroll
            for (int mi = 0; mi < 2; mi++)
#pragma unroll
                for (int ni = 0; ni < 4; ni++) {
                    MMA8(c[mi][ni], al[mi], bh[ni]);
                    MMA8(c[mi][ni], ah[mi], bl[ni]);
                    MMA8(c[mi][ni], ah[mi], bh[ni]);
                }
        }
        __syncthreads();
    }

#pragma unroll
    for (int mi = 0; mi < 2; mi++) {
#pragma unroll
        for (int ni = 0; ni < 4; ni++) {
            int row = bm + wm * 32 + mi * 16 + grp;
            int col = bn + wn * 32 + ni * 8 + 2 * qid;
            if (col >= Nc) continue;
            float bx = bias[col], by = bias[col + 1];
            float v0 = c[mi][ni][0] + bx, v1 = c[mi][ni][1] + by;
            float v2 = c[mi][ni][2] + bx, v3 = c[mi][ni][3] + by;
            if (row < M) {
                *(float2*)&C[(size_t)row * Nc + col] = make_float2(v0, v1);
                Ch[((size_t)row * Nc + col) / 2] = __floats2half2_rn(v0, v1);
            }
            if (row + 8 < M) {
                *(float2*)&C[(size_t)(row + 8) * Nc + col] = make_float2(v2, v3);
                Ch[((size_t)(row + 8) * Nc + col) / 2] = __floats2half2_rn(v2, v3);
            }
        }
    }
}

// ---------------- fp16 GAT GEMM with in-MMA attention dots (R10) --------------
template <int NT, int KC>
__global__ __launch_bounds__(256, 3)
void hgemm_k(const __half* __restrict__ A, const __half* __restrict__ Bt,
             int M,
             __half2* __restrict__ hp16,
             float* __restrict__ as_, float* __restrict__ ad_) {
    constexpr int K = KC;
    constexpr int NTE = NT + 8;
    constexpr int NI = NTE / 8;
    constexpr int AST = 128 * 40;
    constexpr int BST = NTE * 40;
    constexpr int NB4 = NTE * 4;

    extern __shared__ __half smh[];
    __half* Asm = smh;
    __half* Bsm = smh + 2 * AST;
    int tid = threadIdx.x;
    int wid = tid >> 5, lane = tid & 31;
    int grp = lane >> 2, qid = lane & 3;
    int bm = blockIdx.y * 128;
    int hidx = blockIdx.x;
    const __half* Bth = Bt + (size_t)hidx * NTE * K;

    auto ldt = [&](int b, int k0) {
        __half* Ab = Asm + b * AST;
        __half* Bb = Bsm + b * BST;
#pragma unroll
        for (int t = 0; t < 2; t++) {
            int idx = tid + t * 256;
            int row = idx >> 2, c4 = idx & 3;
            int gm = bm + row;
            cp16h(Ab + row * 40 + c4 * 8, A + (size_t)gm * K + k0 + c4 * 8, gm < M);
        }
#pragma unroll
        for (int t = 0; t < (NB4 + 255) / 256; t++) {
            int idx = tid + t * 256;
            if (idx < NB4) {
                int n = idx >> 2, c4 = idx & 3;
                cp16h(Bb + n * 40 + c4 * 8, Bth + (size_t)n * K + k0 + c4 * 8, true);
            }
        }
    };

    float c[NI][4] = {};
    constexpr int nk = K >> 5;
    ldt(0, 0);
    CP_COMMIT();

    for (int t = 0; t < nk; t++) {
        if (t + 1 < nk) {
            ldt((t + 1) & 1, (t + 1) << 5);
            CP_COMMIT();
            CP_WAIT(1);
        } else {
            CP_WAIT(0);
        }
        __syncthreads();
        const __half* Ab = Asm + (t & 1) * AST;
        const __half* Bb = Bsm + (t & 1) * BST;
#pragma unroll
        for (int kk = 0; kk < 32; kk += 16) {
            uint32_t a[4], b[NI][2];
            int r = wid * 16 + grp;
            a[0] = *(const uint32_t*)&Ab[r * 40 + kk + 2 * qid];
            a[1] = *(const uint32_t*)&Ab[(r + 8) * 40 + kk + 2 * qid];
            a[2] = *(const uint32_t*)&Ab[r * 40 + kk + 2 * qid + 8];
            a[3] = *(const uint32_t*)&Ab[(r + 8) * 40 + kk + 2 * qid + 8];
#pragma unroll
            for (int ni = 0; ni < NI; ni++) {
                int cn = ni * 8 + grp;
                b[ni][0] = *(const uint32_t*)&Bb[cn * 40 + kk + 2 * qid];
                b[ni][1] = *(const uint32_t*)&Bb[cn * 40 + kk + 2 * qid + 8];
            }
#pragma unroll
            for (int ni = 0; ni < NI; ni++)
                MMA16(c[ni], a, b[ni]);
        }
        __syncthreads();
    }

    int gr0 = bm + wid * 16 + grp;
    int gr1 = gr0 + 8;
    int bn = hidx * NT;
#pragma unroll
    for (int ni = 0; ni < NI - 1; ni++) {
        int col = bn + ni * 8 + 2 * qid;
        if (gr0 < M) hp16[((size_t)gr0 * (HEADS * NT) + col) / 2] = __floats2half2_rn(c[ni][0], c[ni][1]);
        if (gr1 < M) hp16[((size_t)gr1 * (HEADS * NT) + col) / 2] = __floats2half2_rn(c[ni][2], c[ni][3]);
    }
    {
        float u0 = c[NI - 1][0] + c[NI - 1][1];
        float u1 = c[NI - 1][2] + c[NI - 1][3];
        if (qid == 0) {
            if (gr0 < M) as_[(size_t)gr0 * HEADS + hidx] = u0;
            if (gr1 < M) as_[(size_t)gr1 * HEADS + hidx] = u1;
        } else if (qid == 1) {
            if (gr0 < M) ad_[(size_t)gr0 * HEADS + hidx] = u0;
            if (gr1 < M) ad_[(size_t)gr1 * HEADS + hidx] = u1;
        }
    }
}

// ---------------- layer-1 aggregation: thread-per-(node,octet) ----------------
// 320 threads/block = 8 nodes x 40 octets. Each thread owns one int4 octet and
// its head's alpha chain; no idle lanes, no branches, contiguous int4 loads.
__global__ __launch_bounds__(320)
void gat_aggr1_k(const int4* __restrict__ hp16,
                 const float* __restrict__ as_,
                 const float* __restrict__ ad_,
                 const float* __restrict__ bias,
                 __half* __restrict__ out) {
    const int NO8 = L1F / 8;   // 40
    int t = blockIdx.x * 320 + threadIdx.x;
    int node = t / NO8, oct = t % NO8;
    if (node >= NN) return;
    int h = oct >> 3;          // oct*8/64
    int r0 = g_rowptr[node], r1 = g_rowptr[node + 1];
    float adv = ad_[node * HEADS + h];

    float acc[8] = {};
    float sl = 0.f;

#pragma unroll 4
    for (int j = r0; j < r1; j++) {
        int s = __ldg(&g_csrc[j]);
        float e = __ldg(&as_[s * HEADS + h]) + adv;
        e = (e > 0.f) ? e : 0.2f * e;
        float a = __expf(e);
        sl += a;
        int4 p = __ldg(hp16 + (size_t)s * NO8 + oct);
        float2 f0 = __half22float2(*(__half2*)&p.x);
        float2 f1 = __half22float2(*(__half2*)&p.y);
        float2 f2 = __half22float2(*(__half2*)&p.z);
        float2 f3 = __half22float2(*(__half2*)&p.w);
        acc[0] += a * f0.x; acc[1] += a * f0.y;
        acc[2] += a * f1.x; acc[3] += a * f1.y;
        acc[4] += a * f2.x; acc[5] += a * f2.y;
        acc[6] += a * f3.x; acc[7] += a * f3.y;
    }

    float inv = 1.f / (sl + 1e-16f);
    __half2 hh[4];
#pragma unroll
    for (int k = 0; k < 4; k++) {
        float va = acc[2 * k] * inv + bias[oct * 8 + 2 * k];
        float vb = acc[2 * k + 1] * inv + bias[oct * 8 + 2 * k + 1];
        va = (va > 0.f) ? va : (__expf(va) - 1.f);
        vb = (vb > 0.f) ? vb : (__expf(vb) - 1.f);
        hh[k] = __floats2half2_rn(va, vb);
    }
    int4 st;
    st.x = *(int*)&hh[0]; st.y = *(int*)&hh[1];
    st.z = *(int*)&hh[2]; st.w = *(int*)&hh[3];
    *(int4*)(out + (size_t)node * L1F + oct * 8) = st;
}

// ---------------- layer-2 aggregation + finalize -------------------------------
__global__ void gat_aggr2fin_k(const int4* __restrict__ hp16,
                               const float* __restrict__ as_,
                               const float* __restrict__ ad_,
                               const float* __restrict__ b2,
                               float* __restrict__ logits) {
    const int C = CLS, NO8 = L2F / 8;
    __shared__ float sh[8][L2F];
    int w = (blockIdx.x * blockDim.x + threadIdx.x) >> 5;
    int wl = threadIdx.x >> 5;
    int lane = threadIdx.x & 31;
    if (w >= NN) return;
    int r0 = g_rowptr[w], r1 = g_rowptr[w + 1];

    const int o0 = lane;
    const bool v0 = o0 < NO8;
    const int h0 = v0 ? (o0 * 8) / C : 0;
    const float adv0 = v0 ? ad_[w * HEADS + h0] : 0.f;

    float acc0[8] = {};
    float sl0 = 0.f;

#pragma unroll 4
    for (int j = r0; j < r1; j++) {
        int s = __ldg(&g_csrc[j]);
        if (v0) {
            float e = __ldg(&as_[s * HEADS + h0]) + adv0;
            e = (e > 0.f) ? e : 0.2f * e;
            float a = __expf(e);
            sl0 += a;
            int4 p = __ldg(hp16 + (size_t)s * NO8 + o0);
            float2 f0 = __half22float2(*(__half2*)&p.x);
            float2 f1 = __half22float2(*(__half2*)&p.y);
            float2 f2 = __half22float2(*(__half2*)&p.z);
            float2 f3 = __half22float2(*(__half2*)&p.w);
            acc0[0] += a * f0.x; acc0[1] += a * f0.y;
            acc0[2] += a * f1.x; acc0[3] += a * f1.y;
            acc0[4] += a * f2.x; acc0[5] += a * f2.y;
            acc0[6] += a * f3.x; acc0[7] += a * f3.y;
        }
    }

    if (v0) {
        float inv = 1.f / (sl0 + 1e-16f);
#pragma unroll
        for (int k = 0; k < 8; k++) sh[wl][o0 * 8 + k] = acc0[k] * inv;
    }
    __syncwarp();

    int c0 = lane, c1 = lane + 32;
    bool has1 = (c1 < CLS);
    float a0 = 0.f, a1 = 0.f;
#pragma unroll
    for (int h = 0; h < HEADS; h++) a0 += sh[wl][h * CLS + c0];
    float v0f = a0 * (1.f / HEADS) + b2[c0];
    float v1f = 0.f;
    if (has1) {
#pragma unroll
        for (int h = 0; h < HEADS; h++) a1 += sh[wl][h * CLS + c1];
        v1f = a1 * (1.f / HEADS) + b2[c1];
    }
    float mx = has1 ? fmaxf(v0f, v1f) : v0f;
#pragma unroll
    for (int o = 16; o; o >>= 1) mx = fmaxf(mx, __shfl_xor_sync(0xFFFFFFFFu, mx, o));
    float se = __expf(v0f - mx) + (has1 ? __expf(v1f - mx) : 0.f);
#pragma unroll
    for (int o = 16; o; o >>= 1) se += __shfl_xor_sync(0xFFFFFFFFu, se, o);
    float lse = logf(se) + mx;
    logits[(size_t)w * CLS + c0] = v0f - lse;
    if (has1) logits[(size_t)w * CLS + c1] = v1f - lse;
}

// ---------------- host ----------------------------------------------------------
#define HSMEM_L1 ((2 * 128 * 40 + 2 * (HID + 8) * 40) * 2)
#define HSMEM_L2 ((2 * 128 * 40 + 2 * (CLS + 8) * 40) * 2)

extern "C" void kernel_launch(void* const* d_in, const int* in_sizes, int n_in,
                              void* d_out, int out_size) {
    const float* x     = (const float*)d_in[0];
    const void*  ei    = d_in[1];
    const float* emb_W = (const float*)d_in[2];
    const float* emb_b = (const float*)d_in[3];
    const float* W1    = (const float*)d_in[4];
    const float* at_s1 = (const float*)d_in[5];
    const float* at_d1 = (const float*)d_in[6];
    const float* b1    = (const float*)d_in[7];
    const float* W2    = (const float*)d_in[8];
    const float* at_s2 = (const float*)d_in[9];
    const float* at_d2 = (const float*)d_in[10];
    const float* b2    = (const float*)d_in[11];

    float* outp   = (float*)d_out;
    float* emb    = outp;
    float* logits = outp + (size_t)NN * HID;

    float *as1, *ad1, *as2, *ad2;
    __half *embh, *o1h;
    int4* hp16;
    cudaGetSymbolAddress((void**)&as1,  g_as1);
    cudaGetSymbolAddress((void**)&ad1,  g_ad1);
    cudaGetSymbolAddress((void**)&as2,  g_as2);
    cudaGetSymbolAddress((void**)&ad2,  g_ad2);
    cudaGetSymbolAddress((void**)&embh, g_embh);
    cudaGetSymbolAddress((void**)&o1h,  g_o1h);
    cudaGetSymbolAddress((void**)&hp16, g_hp16);
    __half *w1t, *w2t;
    cudaGetSymbolAddress((void**)&w1t, g_w1t);
    cudaGetSymbolAddress((void**)&w2t, g_w2t);

    cudaFuncSetAttribute(tf32_gemm_k, cudaFuncAttributeMaxDynamicSharedMemorySize, GEMM_SMEM_BYTES);
    cudaFuncSetAttribute(hgemm_k<HID, HID>, cudaFuncAttributeMaxDynamicSharedMemorySize, HSMEM_L1);
    cudaFuncSetAttribute(hgemm_k<CLS, L1F>, cudaFuncAttributeMaxDynamicSharedMemorySize, HSMEM_L2);

    const int T = 256;
    const int MB = (NN + 127) / 128;

    // 0: detect, 1: prep (small), 2: emb tf32 GEMM, 3: hgemm1, then CSR chain.
    detect_dtype_k<<<1, 32>>>(ei);
    prep_k<<<(SEGT + T - 1) / T, T>>>(W1, W2, at_s1, at_d1, at_s2, at_d2);
    tf32_gemm_k<<<dim3(1, MB), 256, GEMM_SMEM_BYTES>>>(
        x, emb_W, emb, emb_b, (__half2*)embh, NN, INC, HID);
    hgemm_k<HID, HID><<<dim3(HEADS, MB), 256, HSMEM_L1>>>(
        embh, w1t, NN, (__half2*)hp16, as1, ad1);

    hist_k<<<(ET + T - 1) / T, T>>>(ei);
    blockscan_k<<<NB, 256>>>();
    bscan2_k<<<1, 256>>>();
    addoff_k<<<(NN + T - 1) / T, T>>>();
    scatter_k<<<(ET + T - 1) / T, T>>>(ei);

    gat_aggr1_k<<<(NN * 40 + 319) / 320, 320>>>(hp16, as1, ad1, b1, o1h);

    hgemm_k<CLS, L1F><<<dim3(HEADS, MB), 256, HSMEM_L2>>>(
        o1h, w2t, NN, (__half2*)hp16, as2, ad2);

    gat_aggr2fin_k<<<(NN * 32 + T - 1) / T, T>>>(hp16, as2, ad2, b2, logits);
}

// round 13
// speedup vs baseline: 1.2876x; 1.0591x over previous
#include <cuda_runtime.h>
#include <cuda_fp16.h>
#include <cstdint>
#include <cstddef>

#define NN    50000
#define EE    800000
#define ET    (EE + NN)
#define INC   128
#define HID   64
#define HEADS 5
#define CLS   40
#define L1F   (HEADS * HID)   // 320
#define L2F   (HEADS * CLS)   // 200
#define NB    ((NN + 255) / 256)
#define W1R   (HID + 8)       // 72
#define W2R   (CLS + 8)       // 48

// ---------------- scratch ----------------------------------------------------
__device__ __half g_o1h [(size_t)NN * L1F];
__device__ int4   g_hp16[(size_t)NN * L1F / 8];
__device__ __half g_w1t [HEADS * W1R * HID];
__device__ __half g_w2t [HEADS * W2R * L1F];
__device__ float  g_as1[NN * HEADS];
__device__ float  g_ad1[NN * HEADS];
__device__ float  g_as2[NN * HEADS];
__device__ float  g_ad2[NN * HEADS];
__device__ int    g_csrc[ET];
__device__ int    g_rowptr[NN + 1];
__device__ int    g_cnt[NN];
__device__ int    g_off[NN];
__device__ int    g_bsum[NB];
__device__ int    g_boff[NB];
__device__ int    g_is64;

// ---------------- dtype detect ------------------------------------------------
__global__ void detect_dtype_k(const void* ei) {
    const int* p = (const int*)ei;
    int t = threadIdx.x;
    int nz = 0;
    for (int i = t; i < 1024; i += 32)
        if (p[2 * i + 1] != 0) nz = 1;
    unsigned m = __ballot_sync(0xFFFFFFFFu, nz);
    if (t == 0) g_is64 = (m == 0) ? 1 : 0;
}

__device__ __forceinline__ void edge_at(const void* ei, int i, int& s, int& d) {
    if (i < EE) {
        if (g_is64) {
            const long long* p = (const long long*)ei;
            s = (int)p[i];
            d = (int)p[EE + i];
        } else {
            const int* p = (const int*)ei;
            s = p[i];
            d = p[EE + i];
        }
    } else {
        s = i - EE;
        d = i - EE;
    }
}

// ---------------- prep: weight conversion + init --------------------------------
#define S0 (HEADS * HID * HID)
#define S1 (S0 + HEADS * HID * 2)
#define S2 (S1 + HEADS * 4 * HID)
#define S3 (S2 + HEADS * CLS * L1F)
#define S4 (S3 + HEADS * L1F * 2)
#define S5 (S4 + HEADS * 4 * L1F)
#define SEGT S5

__global__ void prep_k(const float* __restrict__ W1, const float* __restrict__ W2,
                       const float* __restrict__ as1, const float* __restrict__ ad1,
                       const float* __restrict__ as2, const float* __restrict__ ad2) {
    int i = blockIdx.x * blockDim.x + threadIdx.x;
    if (i < S0) {
        int h = i / (HID * HID), rem = i % (HID * HID);
        int n = rem / HID, k = rem % HID;
        g_w1t[(h * W1R + n) * HID + k] = __float2half(W1[(size_t)k * L1F + h * HID + n]);
    } else if (i < S1) {
        int j = i - S0;
        int h = j / (HID * 2), rem = j % (HID * 2);
        int which = rem / HID, k = rem % HID;
        const float* att = which ? ad1 : as1;
        float v = 0.f;
        for (int n = 0; n < HID; n++)
            v += W1[(size_t)k * L1F + h * HID + n] * att[h * HID + n];
        __half hi = __float2half_rn(v);
        __half lo = __float2half_rn(v - __half2float(hi));
        g_w1t[(h * W1R + HID + which * 2 + 0) * HID + k] = hi;
        g_w1t[(h * W1R + HID + which * 2 + 1) * HID + k] = lo;
    } else if (i < S2) {
        int j = i - S1;
        int h = j / (4 * HID), rem = j % (4 * HID);
        int r = rem / HID, k = rem % HID;
        g_w1t[(h * W1R + HID + 4 + r) * HID + k] = __float2half(0.f);
    } else if (i < S3) {
        int j = i - S2;
        int h = j / (CLS * L1F), rem = j % (CLS * L1F);
        int n = rem / L1F, k = rem % L1F;
        g_w2t[(h * W2R + n) * L1F + k] = __float2half(W2[(size_t)k * L2F + h * CLS + n]);
    } else if (i < S4) {
        int j = i - S3;
        int h = j / (L1F * 2), rem = j % (L1F * 2);
        int which = rem / L1F, k = rem % L1F;
        const float* att = which ? ad2 : as2;
        float v = 0.f;
        for (int n = 0; n < CLS; n++)
            v += W2[(size_t)k * L2F + h * CLS + n] * att[h * CLS + n];
        __half hi = __float2half_rn(v);
        __half lo = __float2half_rn(v - __half2float(hi));
        g_w2t[(h * W2R + CLS + which * 2 + 0) * L1F + k] = hi;
        g_w2t[(h * W2R + CLS + which * 2 + 1) * L1F + k] = lo;
    } else if (i < S5) {
        int j = i - S4;
        int h = j / (4 * L1F), rem = j % (4 * L1F);
        int r = rem / L1F, k = rem % L1F;
        g_w2t[(h * W2R + CLS + 4 + r) * L1F + k] = __float2half(0.f);
    }
    if (i < NN) {
        g_cnt[i] = 0;
        g_off[i] = 0;
    }
}

__global__ void hist_k(const void* ei) {
    int i = blockIdx.x * blockDim.x + threadIdx.x;
    if (i >= ET) return;
    int s, d;
    edge_at(ei, i, s, d);
    atomicAdd(&g_cnt[d], 1);
}

// ---------------- parallel scan --------------------------------------------------
__global__ void blockscan_k() {
    __shared__ int sh[256];
    int b = blockIdx.x, t = threadIdx.x, i = b * 256 + t;
    int v = (i < NN) ? g_cnt[i] : 0;
    sh[t] = v;
    __syncthreads();
#pragma unroll
    for (int o = 1; o < 256; o <<= 1) {
        int u = (t >= o) ? sh[t - o] : 0;
        __syncthreads();
        sh[t] += u;
        __syncthreads();
    }
    if (i < NN) g_rowptr[i] = sh[t] - v;
    if (t == 255) g_bsum[b] = sh[255];
}

__global__ void bscan2_k() {
    __shared__ int sh[256];
    int t = threadIdx.x;
    int v = (t < NB) ? g_bsum[t] : 0;
    sh[t] = v;
    __syncthreads();
#pragma unroll
    for (int o = 1; o < 256; o <<= 1) {
        int u = (t >= o) ? sh[t - o] : 0;
        __syncthreads();
        sh[t] += u;
        __syncthreads();
    }
    if (t < NB) g_boff[t] = sh[t] - v;
}

__global__ void addoff_k() {
    int i = blockIdx.x * blockDim.x + threadIdx.x;
    if (i < NN) g_rowptr[i] += g_boff[i >> 8];
    if (i == 0) g_rowptr[NN] = ET;
}

__global__ void scatter_k(const void* ei) {
    int i = blockIdx.x * blockDim.x + threadIdx.x;
    if (i >= ET) return;
    int s, d;
    edge_at(ei, i, s, d);
    int pos = g_rowptr[d] + atomicAdd(&g_off[d], 1);
    g_csrc[pos] = s;
}

// ---------------- cp.async helpers ----------------------------------------------
__device__ __forceinline__ void cp16(float* dst, const float* src, bool pred) {
    uint32_t s = (uint32_t)__cvta_generic_to_shared(dst);
    int bytes = pred ? 16 : 0;
    asm volatile("cp.async.ca.shared.global [%0], [%1], 16, %2;\n"
                 :: "r"(s), "l"(src), "r"(bytes));
}
__device__ __forceinline__ void cp16h(__half* dst, const __half* src, bool pred) {
    uint32_t s = (uint32_t)__cvta_generic_to_shared(dst);
    int bytes = pred ? 16 : 0;
    asm volatile("cp.async.ca.shared.global [%0], [%1], 16, %2;\n"
                 :: "r"(s), "l"(src), "r"(bytes));
}
#define CP_COMMIT() asm volatile("cp.async.commit_group;\n" ::: "memory")
#define CP_WAIT(n)  asm volatile("cp.async.wait_group %0;\n" :: "n"(n) : "memory")

__device__ __forceinline__ void tf_split(float f, uint32_t& hi, uint32_t& lo) {
    uint32_t u = __float_as_uint(f);
    hi = u & 0xFFFFE000u;
    float r = f - __uint_as_float(hi);
    lo = __float_as_uint(r) & 0xFFFFE000u;
}

#define MMA8(cc, a, b)                                                          \
    asm volatile(                                                               \
        "mma.sync.aligned.m16n8k8.row.col.f32.tf32.tf32.f32 "                   \
        "{%0,%1,%2,%3},{%4,%5,%6,%7},{%8,%9},{%0,%1,%2,%3};\n"                  \
        : "+f"(cc[0]), "+f"(cc[1]), "+f"(cc[2]), "+f"(cc[3])                    \
        : "r"(a[0]), "r"(a[1]), "r"(a[2]), "r"(a[3]), "r"(b[0]), "r"(b[1]))

#define MMA16(cc, a, b)                                                         \
    asm volatile(                                                               \
        "mma.sync.aligned.m16n8k16.row.col.f32.f16.f16.f32 "                    \
        "{%0,%1,%2,%3},{%4,%5,%6,%7},{%8,%9},{%0,%1,%2,%3};\n"                  \
        : "+f"(cc[0]), "+f"(cc[1]), "+f"(cc[2]), "+f"(cc[3])                    \
        : "r"(a[0]), "r"(a[1]), "r"(a[2]), "r"(a[3]), "r"(b[0]), "r"(b[1]))

// ---------------- FUSED emb (tf32x3) + layer-1 (fp16 + in-MMA dots) -----------
// Phase 1: C1 = x(128x128) @ emb_W(128x64) + b  -> fp32 emb out + fp16 in smem.
// Phase 2: for each of 5 heads: hp1_h = C1h @ w1t_h^T (NTE=72 cols incl. dots).
// smem: [0, 59392) phase-1 stages (fp32); B2 (51840 B) overlaps at 0 after
// phase 1; C1A fp16 (18432 B) at offset 59392. Total 77824 B.
#define P1_STAGE_F  (128 * 40)          // fp32 per A stage
#define P1_BSTAGE_F (32 * 72)
#define P1_BYTES    ((2 * P1_STAGE_F + 2 * P1_BSTAGE_F) * 4)   // 59392
#define C1A_OFF     P1_BYTES            // halves region, 128*72*2 = 18432 B
#define FUSED_SMEM  (P1_BYTES + 128 * 72 * 2)

__global__ __launch_bounds__(256, 2)
void fused_emb_l1_k(const float* __restrict__ A, const float* __restrict__ B,
                    float* __restrict__ C, const float* __restrict__ bias,
                    const __half* __restrict__ w1t,
                    __half2* __restrict__ hp16,
                    float* __restrict__ as_, float* __restrict__ ad_, int M) {
    const int K = INC, Nc = HID;
    extern __shared__ char smc[];
    float* Asm = (float*)smc;
    float* Bsm = (float*)smc + 2 * P1_STAGE_F;
    __half* C1A = (__half*)(smc + C1A_OFF);      // [128][72] halves
    __half* B2  = (__half*)smc;                  // [5][72][72] halves (after phase 1)

    int tid = threadIdx.x;
    int wid = tid >> 5, lane = tid & 31;
    int wm = wid & 3, wn = wid >> 2;
    int grp = lane >> 2, qid = lane & 3;
    int bm = blockIdx.x * 128;

    // ---- phase 1: tf32x3 emb GEMM ----
    auto ldt = [&](int b, int k0) {
        float* Ab = Asm + b * P1_STAGE_F;
        float* Bb = Bsm + b * P1_BSTAGE_F;
#pragma unroll
        for (int t = 0; t < 4; t++) {
            int idx = tid + t * 256;
            int row = idx >> 3, c4 = idx & 7;
            int gm = bm + row;
            cp16(Ab + row * 40 + c4 * 4, A + (size_t)gm * K + k0 + c4 * 4, gm < M);
        }
#pragma unroll
        for (int t = 0; t < 2; t++) {
            int idx = tid + t * 256;
            int kk = idx >> 4, n4 = idx & 15;
            cp16(Bb + kk * 72 + n4 * 4, B + (size_t)(k0 + kk) * Nc + n4 * 4, true);
        }
    };

    float c[2][4][4] = {};
    const int nk = K >> 5;   // 4
    ldt(0, 0);
    CP_COMMIT();

    for (int t = 0; t < nk; t++) {
        if (t + 1 < nk) {
            ldt((t + 1) & 1, (t + 1) << 5);
            CP_COMMIT();
            CP_WAIT(1);
        } else {
            CP_WAIT(0);
        }
        __syncthreads();
        const float* Ab = Asm + (t & 1) * P1_STAGE_F;
        const float* Bb = Bsm + (t & 1) * P1_BSTAGE_F;
#pragma unroll
        for (int kk = 0; kk < 32; kk += 8) {
            uint32_t ah[2][4], al[2][4], bh[4][2], bl[4][2];
#pragma unroll
            for (int mi = 0; mi < 2; mi++) {
                int r = wm * 32 + mi * 16 + grp;
                tf_split(Ab[r * 40 + kk + qid],           ah[mi][0], al[mi][0]);
                tf_split(Ab[(r + 8) * 40 + kk + qid],     ah[mi][1], al[mi][1]);
                tf_split(Ab[r * 40 + kk + qid + 4],       ah[mi][2], al[mi][2]);
                tf_split(Ab[(r + 8) * 40 + kk + qid + 4], ah[mi][3], al[mi][3]);
            }
#pragma unroll
            for (int ni = 0; ni < 4; ni++) {
                int cn = wn * 32 + ni * 8 + grp;
                tf_split(Bb[(kk + qid) * 72 + cn],     bh[ni][0], bl[ni][0]);
                tf_split(Bb[(kk + qid + 4) * 72 + cn], bh[ni][1], bl[ni][1]);
            }
#pragma unroll
            for (int mi = 0; mi < 2; mi++)
#pragma unroll
                for (int ni = 0; ni < 4; ni++) {
                    MMA8(c[mi][ni], al[mi], bh[ni]);
                    MMA8(c[mi][ni], ah[mi], bl[ni]);
                    MMA8(c[mi][ni], ah[mi], bh[ni]);
                }
        }
        __syncthreads();
    }

    // ---- phase-1 epilogue: fp32 out + fp16 -> C1A smem; prefetch B2 ----
    // B2: 5 heads x 72 rows x 64 halves -> smem stride 72 halves
    {
        const int CH = HEADS * W1R * 8;   // 2880 16B chunks
        for (int i = tid; i < CH; i += 256) {
            int h = i / (W1R * 8), rem = i % (W1R * 8);
            int n = rem >> 3, c8 = rem & 7;
            cp16h(B2 + ((size_t)h * W1R + n) * 72 + c8 * 8,
                  w1t + ((size_t)h * W1R + n) * HID + c8 * 8, true);
        }
        CP_COMMIT();
    }
#pragma unroll
    for (int mi = 0; mi < 2; mi++) {
#pragma unroll
        for (int ni = 0; ni < 4; ni++) {
            int lr = wm * 32 + mi * 16 + grp;
            int row = bm + lr;
            int col = wn * 32 + ni * 8 + 2 * qid;
            float bx = bias[col], by = bias[col + 1];
            float v0 = c[mi][ni][0] + bx, v1 = c[mi][ni][1] + by;
            float v2 = c[mi][ni][2] + bx, v3 = c[mi][ni][3] + by;
            *(__half2*)&C1A[lr * 72 + col]       = __floats2half2_rn(v0, v1);
            *(__half2*)&C1A[(lr + 8) * 72 + col] = __floats2half2_rn(v2, v3);
            if (row < M)     *(float2*)&C[(size_t)row * Nc + col]       = make_float2(v0, v1);
            if (row + 8 < M) *(float2*)&C[(size_t)(row + 8) * Nc + col] = make_float2(v2, v3);
        }
    }
    CP_WAIT(0);
    __syncthreads();

    // ---- phase 2: per-head fp16 MMA (NTE=72 incl. att cols), K=64 resident ----
    int r = wid * 16 + grp;      // local row base for this thread's A frags
    int gr0 = bm + r, gr1 = gr0 + 8;
#pragma unroll
    for (int h = 0; h < HEADS; h++) {
        const __half* Bh = B2 + (size_t)h * W1R * 72;
        float c2[9][4] = {};
#pragma unroll
        for (int kk = 0; kk < 64; kk += 16) {
            uint32_t a[4], b[9][2];
            a[0] = *(const uint32_t*)&C1A[r * 72 + kk + 2 * qid];
            a[1] = *(const uint32_t*)&C1A[(r + 8) * 72 + kk + 2 * qid];
            a[2] = *(const uint32_t*)&C1A[r * 72 + kk + 2 * qid + 8];
            a[3] = *(const uint32_t*)&C1A[(r + 8) * 72 + kk + 2 * qid + 8];
#pragma unroll
            for (int ni = 0; ni < 9; ni++) {
                int cn = ni * 8 + grp;
                b[ni][0] = *(const uint32_t*)&Bh[cn * 72 + kk + 2 * qid];
                b[ni][1] = *(const uint32_t*)&Bh[cn * 72 + kk + 2 * qid + 8];
            }
#pragma unroll
            for (int ni = 0; ni < 9; ni++)
                MMA16(c2[ni], a, b[ni]);
        }
        // epilogue for this head
        int bn = h * HID;
#pragma unroll
        for (int ni = 0; ni < 8; ni++) {
            int col = bn + ni * 8 + 2 * qid;
            if (gr0 < M) hp16[((size_t)gr0 * L1F + col) / 2] = __floats2half2_rn(c2[ni][0], c2[ni][1]);
            if (gr1 < M) hp16[((size_t)gr1 * L1F + col) / 2] = __floats2half2_rn(c2[ni][2], c2[ni][3]);
        }
        float u0 = c2[8][0] + c2[8][1];
        float u1 = c2[8][2] + c2[8][3];
        if (qid == 0) {
            if (gr0 < M) as_[(size_t)gr0 * HEADS + h] = u0;
            if (gr1 < M) as_[(size_t)gr1 * HEADS + h] = u1;
        } else if (qid == 1) {
            if (gr0 < M) ad_[(size_t)gr0 * HEADS + h] = u0;
            if (gr1 < M) ad_[(size_t)gr1 * HEADS + h] = u1;
        }
    }
}

// ---------------- layer-2 fp16 GEMM with in-MMA dots (R10) --------------------
template <int NT, int KC>
__global__ __launch_bounds__(256, 3)
void hgemm_k(const __half* __restrict__ A, const __half* __restrict__ Bt,
             int M,
             __half2* __restrict__ hp16,
             float* __restrict__ as_, float* __restrict__ ad_) {
    constexpr int K = KC;
    constexpr int NTE = NT + 8;
    constexpr int NI = NTE / 8;
    constexpr int AST = 128 * 40;
    constexpr int BST = NTE * 40;
    constexpr int NB4 = NTE * 4;

    extern __shared__ __half smh[];
    __half* Asm = smh;
    __half* Bsm = smh + 2 * AST;
    int tid = threadIdx.x;
    int wid = tid >> 5, lane = tid & 31;
    int grp = lane >> 2, qid = lane & 3;
    int bm = blockIdx.y * 128;
    int hidx = blockIdx.x;
    const __half* Bth = Bt + (size_t)hidx * NTE * K;

    auto ldt = [&](int b, int k0) {
        __half* Ab = Asm + b * AST;
        __half* Bb = Bsm + b * BST;
#pragma unroll
        for (int t = 0; t < 2; t++) {
            int idx = tid + t * 256;
            int row = idx >> 2, c4 = idx & 3;
            int gm = bm + row;
            cp16h(Ab + row * 40 + c4 * 8, A + (size_t)gm * K + k0 + c4 * 8, gm < M);
        }
#pragma unroll
        for (int t = 0; t < (NB4 + 255) / 256; t++) {
            int idx = tid + t * 256;
            if (idx < NB4) {
                int n = idx >> 2, c4 = idx & 3;
                cp16h(Bb + n * 40 + c4 * 8, Bth + (size_t)n * K + k0 + c4 * 8, true);
            }
        }
    };

    float c[NI][4] = {};
    constexpr int nk = K >> 5;
    ldt(0, 0);
    CP_COMMIT();

    for (int t = 0; t < nk; t++) {
        if (t + 1 < nk) {
            ldt((t + 1) & 1, (t + 1) << 5);
            CP_COMMIT();
            CP_WAIT(1);
        } else {
            CP_WAIT(0);
        }
        __syncthreads();
        const __half* Ab = Asm + (t & 1) * AST;
        const __half* Bb = Bsm + (t & 1) * BST;
#pragma unroll
        for (int kk = 0; kk < 32; kk += 16) {
            uint32_t a[4], b[NI][2];
            int r = wid * 16 + grp;
            a[0] = *(const uint32_t*)&Ab[r * 40 + kk + 2 * qid];
            a[1] = *(const uint32_t*)&Ab[(r + 8) * 40 + kk + 2 * qid];
            a[2] = *(const uint32_t*)&Ab[r * 40 + kk + 2 * qid + 8];
            a[3] = *(const uint32_t*)&Ab[(r + 8) * 40 + kk + 2 * qid + 8];
#pragma unroll
            for (int ni = 0; ni < NI; ni++) {
                int cn = ni * 8 + grp;
                b[ni][0] = *(const uint32_t*)&Bb[cn * 40 + kk + 2 * qid];
                b[ni][1] = *(const uint32_t*)&Bb[cn * 40 + kk + 2 * qid + 8];
            }
#pragma unroll
            for (int ni = 0; ni < NI; ni++)
                MMA16(c[ni], a, b[ni]);
        }
        __syncthreads();
    }

    int gr0 = bm + wid * 16 + grp;
    int gr1 = gr0 + 8;
    int bn = hidx * NT;
#pragma unroll
    for (int ni = 0; ni < NI - 1; ni++) {
        int col = bn + ni * 8 + 2 * qid;
        if (gr0 < M) hp16[((size_t)gr0 * (HEADS * NT) + col) / 2] = __floats2half2_rn(c[ni][0], c[ni][1]);
        if (gr1 < M) hp16[((size_t)gr1 * (HEADS * NT) + col) / 2] = __floats2half2_rn(c[ni][2], c[ni][3]);
    }
    {
        float u0 = c[NI - 1][0] + c[NI - 1][1];
        float u1 = c[NI - 1][2] + c[NI - 1][3];
        if (qid == 0) {
            if (gr0 < M) as_[(size_t)gr0 * HEADS + hidx] = u0;
            if (gr1 < M) as_[(size_t)gr1 * HEADS + hidx] = u1;
        } else if (qid == 1) {
            if (gr0 < M) ad_[(size_t)gr0 * HEADS + hidx] = u0;
            if (gr1 < M) ad_[(size_t)gr1 * HEADS + hidx] = u1;
        }
    }
}

// ---------------- layer-1 aggregation: thread-per-(node,octet) -----------------
__global__ __launch_bounds__(320)
void gat_aggr1_k(const int4* __restrict__ hp16,
                 const float* __restrict__ as_,
                 const float* __restrict__ ad_,
                 const float* __restrict__ bias,
                 __half* __restrict__ out) {
    const int NO8 = L1F / 8;   // 40
    int t = blockIdx.x * 320 + threadIdx.x;
    int node = t / NO8, oct = t % NO8;
    if (node >= NN) return;
    int h = oct >> 3;
    int r0 = g_rowptr[node], r1 = g_rowptr[node + 1];
    float adv = ad_[node * HEADS + h];

    float acc[8] = {};
    float sl = 0.f;

#pragma unroll 4
    for (int j = r0; j < r1; j++) {
        int s = __ldg(&g_csrc[j]);
        float e = __ldg(&as_[s * HEADS + h]) + adv;
        e = (e > 0.f) ? e : 0.2f * e;
        float a = __expf(e);
        sl += a;
        int4 p = __ldg(hp16 + (size_t)s * NO8 + oct);
        float2 f0 = __half22float2(*(__half2*)&p.x);
        float2 f1 = __half22float2(*(__half2*)&p.y);
        float2 f2 = __half22float2(*(__half2*)&p.z);
        float2 f3 = __half22float2(*(__half2*)&p.w);
        acc[0] += a * f0.x; acc[1] += a * f0.y;
        acc[2] += a * f1.x; acc[3] += a * f1.y;
        acc[4] += a * f2.x; acc[5] += a * f2.y;
        acc[6] += a * f3.x; acc[7] += a * f3.y;
    }

    float inv = 1.f / (sl + 1e-16f);
    __half2 hh[4];
#pragma unroll
    for (int k = 0; k < 4; k++) {
        float va = acc[2 * k] * inv + bias[oct * 8 + 2 * k];
        float vb = acc[2 * k + 1] * inv + bias[oct * 8 + 2 * k + 1];
        va = (va > 0.f) ? va : (__expf(va) - 1.f);
        vb = (vb > 0.f) ? vb : (__expf(vb) - 1.f);
        hh[k] = __floats2half2_rn(va, vb);
    }
    int4 st;
    st.x = *(int*)&hh[0]; st.y = *(int*)&hh[1];
    st.z = *(int*)&hh[2]; st.w = *(int*)&hh[3];
    *(int4*)(out + (size_t)node * L1F + oct * 8) = st;
}

// ---------------- layer-2 aggregation + finalize --------------------------------
__global__ void gat_aggr2fin_k(const int4* __restrict__ hp16,
                               const float* __restrict__ as_,
                               const float* __restrict__ ad_,
                               const float* __restrict__ b2,
                               float* __restrict__ logits) {
    const int C = CLS, NO8 = L2F / 8;
    __shared__ float sh[8][L2F];
    int w = (blockIdx.x * blockDim.x + threadIdx.x) >> 5;
    int wl = threadIdx.x >> 5;
    int lane = threadIdx.x & 31;
    if (w >= NN) return;
    int r0 = g_rowptr[w], r1 = g_rowptr[w + 1];

    const int o0 = lane;
    const bool v0 = o0 < NO8;
    const int h0 = v0 ? (o0 * 8) / C : 0;
    const float adv0 = v0 ? ad_[w * HEADS + h0] : 0.f;

    float acc0[8] = {};
    float sl0 = 0.f;

#pragma unroll 4
    for (int j = r0; j < r1; j++) {
        int s = __ldg(&g_csrc[j]);
        if (v0) {
            float e = __ldg(&as_[s * HEADS + h0]) + adv0;
            e = (e > 0.f) ? e : 0.2f * e;
            float a = __expf(e);
            sl0 += a;
            int4 p = __ldg(hp16 + (size_t)s * NO8 + o0);
            float2 f0 = __half22float2(*(__half2*)&p.x);
            float2 f1 = __half22float2(*(__half2*)&p.y);
            float2 f2 = __half22float2(*(__half2*)&p.z);
            float2 f3 = __half22float2(*(__half2*)&p.w);
            acc0[0] += a * f0.x; acc0[1] += a * f0.y;
            acc0[2] += a * f1.x; acc0[3] += a * f1.y;
            acc0[4] += a * f2.x; acc0[5] += a * f2.y;
            acc0[6] += a * f3.x; acc0[7] += a * f3.y;
        }
    }

    if (v0) {
        float inv = 1.f / (sl0 + 1e-16f);
#pragma unroll
        for (int k = 0; k < 8; k++) sh[wl][o0 * 8 + k] = acc0[k] * inv;
    }
    __syncwarp();

    int c0 = lane, c1 = lane + 32;
    bool has1 = (c1 < CLS);
    float a0 = 0.f, a1 = 0.f;
#pragma unroll
    for (int h = 0; h < HEADS; h++) a0 += sh[wl][h * CLS + c0];
    float v0f = a0 * (1.f / HEADS) + b2[c0];
    float v1f = 0.f;
    if (has1) {
#pragma unroll
        for (int h = 0; h < HEADS; h++) a1 += sh[wl][h * CLS + c1];
        v1f = a1 * (1.f / HEADS) + b2[c1];
    }
    float mx = has1 ? fmaxf(v0f, v1f) : v0f;
#pragma unroll
    for (int o = 16; o; o >>= 1) mx = fmaxf(mx, __shfl_xor_sync(0xFFFFFFFFu, mx, o));
    float se = __expf(v0f - mx) + (has1 ? __expf(v1f - mx) : 0.f);
#pragma unroll
    for (int o = 16; o; o >>= 1) se += __shfl_xor_sync(0xFFFFFFFFu, se, o);
    float lse = logf(se) + mx;
    logits[(size_t)w * CLS + c0] = v0f - lse;
    if (has1) logits[(size_t)w * CLS + c1] = v1f - lse;
}

// ---------------- host ------------------------------------------------------------
#define HSMEM_L2 ((2 * 128 * 40 + 2 * (CLS + 8) * 40) * 2)

extern "C" void kernel_launch(void* const* d_in, const int* in_sizes, int n_in,
                              void* d_out, int out_size) {
    const float* x     = (const float*)d_in[0];
    const void*  ei    = d_in[1];
    const float* emb_W = (const float*)d_in[2];
    const float* emb_b = (const float*)d_in[3];
    const float* W1    = (const float*)d_in[4];
    const float* at_s1 = (const float*)d_in[5];
    const float* at_d1 = (const float*)d_in[6];
    const float* b1    = (const float*)d_in[7];
    const float* W2    = (const float*)d_in[8];
    const float* at_s2 = (const float*)d_in[9];
    const float* at_d2 = (const float*)d_in[10];
    const float* b2    = (const float*)d_in[11];

    float* outp   = (float*)d_out;
    float* emb    = outp;
    float* logits = outp + (size_t)NN * HID;

    float *as1, *ad1, *as2, *ad2;
    __half *o1h, *w1t, *w2t;
    int4* hp16;
    cudaGetSymbolAddress((void**)&as1,  g_as1);
    cudaGetSymbolAddress((void**)&ad1,  g_ad1);
    cudaGetSymbolAddress((void**)&as2,  g_as2);
    cudaGetSymbolAddress((void**)&ad2,  g_ad2);
    cudaGetSymbolAddress((void**)&o1h,  g_o1h);
    cudaGetSymbolAddress((void**)&w1t,  g_w1t);
    cudaGetSymbolAddress((void**)&w2t,  g_w2t);
    cudaGetSymbolAddress((void**)&hp16, g_hp16);

    cudaFuncSetAttribute(fused_emb_l1_k, cudaFuncAttributeMaxDynamicSharedMemorySize, FUSED_SMEM);
    cudaFuncSetAttribute(hgemm_k<CLS, L1F>, cudaFuncAttributeMaxDynamicSharedMemorySize, HSMEM_L2);

    const int T = 256;
    const int MB = (NN + 127) / 128;

    // 0: detect, 1: prep, 2: fused emb+layer1 (profiled region), then CSR chain.
    detect_dtype_k<<<1, 32>>>(ei);
    prep_k<<<(SEGT + T - 1) / T, T>>>(W1, W2, at_s1, at_d1, at_s2, at_d2);
    fused_emb_l1_k<<<MB, 256, FUSED_SMEM>>>(
        x, emb_W, emb, emb_b, w1t, (__half2*)hp16, as1, ad1, NN);

    hist_k<<<(ET + T - 1) / T, T>>>(ei);
    blockscan_k<<<NB, 256>>>();
    bscan2_k<<<1, 256>>>();
    addoff_k<<<(NN + T - 1) / T, T>>>();
    scatter_k<<<(ET + T - 1) / T, T>>>(ei);

    gat_aggr1_k<<<(NN * 40 + 319) / 320, 320>>>(hp16, as1, ad1, b1, o1h);

    hgemm_k<CLS, L1F><<<dim3(HEADS, MB), 256, HSMEM_L2>>>(
        o1h, w2t, NN, (__half2*)hp16, as2, ad2);

    gat_aggr2fin_k<<<(NN * 32 + T - 1) / T, T>>>(hp16, as2, ad2, b2, logits);
}

// round 14
// speedup vs baseline: 1.3458x; 1.0452x over previous
#include <cuda_runtime.h>
#include <cuda_fp16.h>
#include <cstdint>
#include <cstddef>

#define NN    50000
#define EE    800000
#define ET    (EE + NN)
#define INC   128
#define HID   64
#define HEADS 5
#define CLS   40
#define L1F   (HEADS * HID)   // 320
#define L2F   (HEADS * CLS)   // 200
#define NB    ((NN + 255) / 256)
#define W1R   (HID + 8)       // 72
#define W2R   (CLS + 8)       // 48

// ---------------- scratch ----------------------------------------------------
__device__ __half g_o1h [(size_t)NN * L1F];
__device__ int4   g_hp16[(size_t)NN * L1F / 8];
__device__ __half g_w1t [HEADS * W1R * HID];
__device__ __half g_w2t [HEADS * W2R * L1F];
__device__ float  g_as1[NN * HEADS];
__device__ float  g_ad1[NN * HEADS];
__device__ float  g_as2[NN * HEADS];
__device__ float  g_ad2[NN * HEADS];
__device__ int    g_csrc[ET];
__device__ int    g_rowptr[NN + 1];
__device__ int    g_cnt[NN];
__device__ int    g_off[NN];
__device__ int    g_bsum[NB];
__device__ int    g_boff[NB];
__device__ int    g_is64;

// ---------------- dtype detect ------------------------------------------------
__global__ void detect_dtype_k(const void* ei) {
    const int* p = (const int*)ei;
    int t = threadIdx.x;
    int nz = 0;
    for (int i = t; i < 1024; i += 32)
        if (p[2 * i + 1] != 0) nz = 1;
    unsigned m = __ballot_sync(0xFFFFFFFFu, nz);
    if (t == 0) g_is64 = (m == 0) ? 1 : 0;
}

__device__ __forceinline__ void edge_at(const void* ei, int i, int& s, int& d) {
    if (i < EE) {
        if (g_is64) {
            const long long* p = (const long long*)ei;
            s = (int)p[i];
            d = (int)p[EE + i];
        } else {
            const int* p = (const int*)ei;
            s = p[i];
            d = p[EE + i];
        }
    } else {
        s = i - EE;
        d = i - EE;
    }
}

// ---------------- prep: weight conversion + init --------------------------------
#define S0 (HEADS * HID * HID)
#define S1 (S0 + HEADS * HID * 2)
#define S2 (S1 + HEADS * 4 * HID)
#define S3 (S2 + HEADS * CLS * L1F)
#define S4 (S3 + HEADS * L1F * 2)
#define S5 (S4 + HEADS * 4 * L1F)
#define SEGT S5

__global__ void prep_k(const float* __restrict__ W1, const float* __restrict__ W2,
                       const float* __restrict__ as1, const float* __restrict__ ad1,
                       const float* __restrict__ as2, const float* __restrict__ ad2) {
    int i = blockIdx.x * blockDim.x + threadIdx.x;
    if (i < S0) {
        int h = i / (HID * HID), rem = i % (HID * HID);
        int n = rem / HID, k = rem % HID;
        g_w1t[(h * W1R + n) * HID + k] = __float2half(W1[(size_t)k * L1F + h * HID + n]);
    } else if (i < S1) {
        int j = i - S0;
        int h = j / (HID * 2), rem = j % (HID * 2);
        int which = rem / HID, k = rem % HID;
        const float* att = which ? ad1 : as1;
        float v = 0.f;
        for (int n = 0; n < HID; n++)
            v += W1[(size_t)k * L1F + h * HID + n] * att[h * HID + n];
        __half hi = __float2half_rn(v);
        __half lo = __float2half_rn(v - __half2float(hi));
        g_w1t[(h * W1R + HID + which * 2 + 0) * HID + k] = hi;
        g_w1t[(h * W1R + HID + which * 2 + 1) * HID + k] = lo;
    } else if (i < S2) {
        int j = i - S1;
        int h = j / (4 * HID), rem = j % (4 * HID);
        int r = rem / HID, k = rem % HID;
        g_w1t[(h * W1R + HID + 4 + r) * HID + k] = __float2half(0.f);
    } else if (i < S3) {
        int j = i - S2;
        int h = j / (CLS * L1F), rem = j % (CLS * L1F);
        int n = rem / L1F, k = rem % L1F;
        g_w2t[(h * W2R + n) * L1F + k] = __float2half(W2[(size_t)k * L2F + h * CLS + n]);
    } else if (i < S4) {
        int j = i - S3;
        int h = j / (L1F * 2), rem = j % (L1F * 2);
        int which = rem / L1F, k = rem % L1F;
        const float* att = which ? ad2 : as2;
        float v = 0.f;
        for (int n = 0; n < CLS; n++)
            v += W2[(size_t)k * L2F + h * CLS + n] * att[h * CLS + n];
        __half hi = __float2half_rn(v);
        __half lo = __float2half_rn(v - __half2float(hi));
        g_w2t[(h * W2R + CLS + which * 2 + 0) * L1F + k] = hi;
        g_w2t[(h * W2R + CLS + which * 2 + 1) * L1F + k] = lo;
    } else if (i < S5) {
        int j = i - S4;
        int h = j / (4 * L1F), rem = j % (4 * L1F);
        int r = rem / L1F, k = rem % L1F;
        g_w2t[(h * W2R + CLS + 4 + r) * L1F + k] = __float2half(0.f);
    }
    if (i < NN) {
        g_cnt[i] = 0;
        g_off[i] = 0;
    }
}

__global__ void hist_k(const void* ei) {
    int i = blockIdx.x * blockDim.x + threadIdx.x;
    if (i >= ET) return;
    int s, d;
    edge_at(ei, i, s, d);
    atomicAdd(&g_cnt[d], 1);
}

// ---------------- parallel scan --------------------------------------------------
__global__ void blockscan_k() {
    __shared__ int sh[256];
    int b = blockIdx.x, t = threadIdx.x, i = b * 256 + t;
    int v = (i < NN) ? g_cnt[i] : 0;
    sh[t] = v;
    __syncthreads();
#pragma unroll
    for (int o = 1; o < 256; o <<= 1) {
        int u = (t >= o) ? sh[t - o] : 0;
        __syncthreads();
        sh[t] += u;
        __syncthreads();
    }
    if (i < NN) g_rowptr[i] = sh[t] - v;
    if (t == 255) g_bsum[b] = sh[255];
}

__global__ void bscan2_k() {
    __shared__ int sh[256];
    int t = threadIdx.x;
    int v = (t < NB) ? g_bsum[t] : 0;
    sh[t] = v;
    __syncthreads();
#pragma unroll
    for (int o = 1; o < 256; o <<= 1) {
        int u = (t >= o) ? sh[t - o] : 0;
        __syncthreads();
        sh[t] += u;
        __syncthreads();
    }
    if (t < NB) g_boff[t] = sh[t] - v;
}

__global__ void addoff_k() {
    int i = blockIdx.x * blockDim.x + threadIdx.x;
    if (i < NN) g_rowptr[i] += g_boff[i >> 8];
    if (i == 0) g_rowptr[NN] = ET;
}

__global__ void scatter_k(const void* ei) {
    int i = blockIdx.x * blockDim.x + threadIdx.x;
    if (i >= ET) return;
    int s, d;
    edge_at(ei, i, s, d);
    int pos = g_rowptr[d] + atomicAdd(&g_off[d], 1);
    g_csrc[pos] = s;
}

// ---------------- cp.async helpers ----------------------------------------------
__device__ __forceinline__ void cp16(float* dst, const float* src, bool pred) {
    uint32_t s = (uint32_t)__cvta_generic_to_shared(dst);
    int bytes = pred ? 16 : 0;
    asm volatile("cp.async.ca.shared.global [%0], [%1], 16, %2;\n"
                 :: "r"(s), "l"(src), "r"(bytes));
}
__device__ __forceinline__ void cp16h(__half* dst, const __half* src, bool pred) {
    uint32_t s = (uint32_t)__cvta_generic_to_shared(dst);
    int bytes = pred ? 16 : 0;
    asm volatile("cp.async.ca.shared.global [%0], [%1], 16, %2;\n"
                 :: "r"(s), "l"(src), "r"(bytes));
}
#define CP_COMMIT() asm volatile("cp.async.commit_group;\n" ::: "memory")
#define CP_WAIT(n)  asm volatile("cp.async.wait_group %0;\n" :: "n"(n) : "memory")

__device__ __forceinline__ void tf_split(float f, uint32_t& hi, uint32_t& lo) {
    uint32_t u = __float_as_uint(f);
    hi = u & 0xFFFFE000u;
    float r = f - __uint_as_float(hi);
    lo = __float_as_uint(r) & 0xFFFFE000u;
}

#define MMA8(cc, a, b)                                                          \
    asm volatile(                                                               \
        "mma.sync.aligned.m16n8k8.row.col.f32.tf32.tf32.f32 "                   \
        "{%0,%1,%2,%3},{%4,%5,%6,%7},{%8,%9},{%0,%1,%2,%3};\n"                  \
        : "+f"(cc[0]), "+f"(cc[1]), "+f"(cc[2]), "+f"(cc[3])                    \
        : "r"(a[0]), "r"(a[1]), "r"(a[2]), "r"(a[3]), "r"(b[0]), "r"(b[1]))

#define MMA16(cc, a, b)                                                         \
    asm volatile(                                                               \
        "mma.sync.aligned.m16n8k16.row.col.f32.f16.f16.f32 "                    \
        "{%0,%1,%2,%3},{%4,%5,%6,%7},{%8,%9},{%0,%1,%2,%3};\n"                  \
        : "+f"(cc[0]), "+f"(cc[1]), "+f"(cc[2]), "+f"(cc[3])                    \
        : "r"(a[0]), "r"(a[1]), "r"(a[2]), "r"(a[3]), "r"(b[0]), "r"(b[1]))

// ---------------- FUSED emb (tf32x3) + layer-1 (fp16 + in-MMA dots) -----------
#define P1_STAGE_F  (128 * 40)
#define P1_BSTAGE_F (32 * 72)
#define P1_BYTES    ((2 * P1_STAGE_F + 2 * P1_BSTAGE_F) * 4)   // 59392
#define C1A_OFF     P1_BYTES
#define FUSED_SMEM  (P1_BYTES + 128 * 72 * 2)

__global__ __launch_bounds__(256, 2)
void fused_emb_l1_k(const float* __restrict__ A, const float* __restrict__ B,
                    float* __restrict__ C, const float* __restrict__ bias,
                    const __half* __restrict__ w1t,
                    __half2* __restrict__ hp16,
                    float* __restrict__ as_, float* __restrict__ ad_, int M) {
    const int K = INC, Nc = HID;
    extern __shared__ char smc[];
    float* Asm = (float*)smc;
    float* Bsm = (float*)smc + 2 * P1_STAGE_F;
    __half* C1A = (__half*)(smc + C1A_OFF);
    __half* B2  = (__half*)smc;

    int tid = threadIdx.x;
    int wid = tid >> 5, lane = tid & 31;
    int wm = wid & 3, wn = wid >> 2;
    int grp = lane >> 2, qid = lane & 3;
    int bm = blockIdx.x * 128;

    auto ldt = [&](int b, int k0) {
        float* Ab = Asm + b * P1_STAGE_F;
        float* Bb = Bsm + b * P1_BSTAGE_F;
#pragma unroll
        for (int t = 0; t < 4; t++) {
            int idx = tid + t * 256;
            int row = idx >> 3, c4 = idx & 7;
            int gm = bm + row;
            cp16(Ab + row * 40 + c4 * 4, A + (size_t)gm * K + k0 + c4 * 4, gm < M);
        }
#pragma unroll
        for (int t = 0; t < 2; t++) {
            int idx = tid + t * 256;
            int kk = idx >> 4, n4 = idx & 15;
            cp16(Bb + kk * 72 + n4 * 4, B + (size_t)(k0 + kk) * Nc + n4 * 4, true);
        }
    };

    float c[2][4][4] = {};
    const int nk = K >> 5;
    ldt(0, 0);
    CP_COMMIT();

    for (int t = 0; t < nk; t++) {
        if (t + 1 < nk) {
            ldt((t + 1) & 1, (t + 1) << 5);
            CP_COMMIT();
            CP_WAIT(1);
        } else {
            CP_WAIT(0);
        }
        __syncthreads();
        const float* Ab = Asm + (t & 1) * P1_STAGE_F;
        const float* Bb = Bsm + (t & 1) * P1_BSTAGE_F;
#pragma unroll
        for (int kk = 0; kk < 32; kk += 8) {
            uint32_t ah[2][4], al[2][4], bh[4][2], bl[4][2];
#pragma unroll
            for (int mi = 0; mi < 2; mi++) {
                int r = wm * 32 + mi * 16 + grp;
                tf_split(Ab[r * 40 + kk + qid],           ah[mi][0], al[mi][0]);
                tf_split(Ab[(r + 8) * 40 + kk + qid],     ah[mi][1], al[mi][1]);
                tf_split(Ab[r * 40 + kk + qid + 4],       ah[mi][2], al[mi][2]);
                tf_split(Ab[(r + 8) * 40 + kk + qid + 4], ah[mi][3], al[mi][3]);
            }
#pragma unroll
            for (int ni = 0; ni < 4; ni++) {
                int cn = wn * 32 + ni * 8 + grp;
                tf_split(Bb[(kk + qid) * 72 + cn],     bh[ni][0], bl[ni][0]);
                tf_split(Bb[(kk + qid + 4) * 72 + cn], bh[ni][1], bl[ni][1]);
            }
#pragma unroll
            for (int mi = 0; mi < 2; mi++)
#pragma unroll
                for (int ni = 0; ni < 4; ni++) {
                    MMA8(c[mi][ni], al[mi], bh[ni]);
                    MMA8(c[mi][ni], ah[mi], bl[ni]);
                    MMA8(c[mi][ni], ah[mi], bh[ni]);
                }
        }
        __syncthreads();
    }

    {
        const int CH = HEADS * W1R * 8;
        for (int i = tid; i < CH; i += 256) {
            int h = i / (W1R * 8), rem = i % (W1R * 8);
            int n = rem >> 3, c8 = rem & 7;
            cp16h(B2 + ((size_t)h * W1R + n) * 72 + c8 * 8,
                  w1t + ((size_t)h * W1R + n) * HID + c8 * 8, true);
        }
        CP_COMMIT();
    }
#pragma unroll
    for (int mi = 0; mi < 2; mi++) {
#pragma unroll
        for (int ni = 0; ni < 4; ni++) {
            int lr = wm * 32 + mi * 16 + grp;
            int row = bm + lr;
            int col = wn * 32 + ni * 8 + 2 * qid;
            float bx = bias[col], by = bias[col + 1];
            float v0 = c[mi][ni][0] + bx, v1 = c[mi][ni][1] + by;
            float v2 = c[mi][ni][2] + bx, v3 = c[mi][ni][3] + by;
            *(__half2*)&C1A[lr * 72 + col]       = __floats2half2_rn(v0, v1);
            *(__half2*)&C1A[(lr + 8) * 72 + col] = __floats2half2_rn(v2, v3);
            if (row < M)     *(float2*)&C[(size_t)row * Nc + col]       = make_float2(v0, v1);
            if (row + 8 < M) *(float2*)&C[(size_t)(row + 8) * Nc + col] = make_float2(v2, v3);
        }
    }
    CP_WAIT(0);
    __syncthreads();

    int r = wid * 16 + grp;
    int gr0 = bm + r, gr1 = gr0 + 8;
#pragma unroll
    for (int h = 0; h < HEADS; h++) {
        const __half* Bh = B2 + (size_t)h * W1R * 72;
        float c2[9][4] = {};
#pragma unroll
        for (int kk = 0; kk < 64; kk += 16) {
            uint32_t a[4], b[9][2];
            a[0] = *(const uint32_t*)&C1A[r * 72 + kk + 2 * qid];
            a[1] = *(const uint32_t*)&C1A[(r + 8) * 72 + kk + 2 * qid];
            a[2] = *(const uint32_t*)&C1A[r * 72 + kk + 2 * qid + 8];
            a[3] = *(const uint32_t*)&C1A[(r + 8) * 72 + kk + 2 * qid + 8];
#pragma unroll
            for (int ni = 0; ni < 9; ni++) {
                int cn = ni * 8 + grp;
                b[ni][0] = *(const uint32_t*)&Bh[cn * 72 + kk + 2 * qid];
                b[ni][1] = *(const uint32_t*)&Bh[cn * 72 + kk + 2 * qid + 8];
            }
#pragma unroll
            for (int ni = 0; ni < 9; ni++)
                MMA16(c2[ni], a, b[ni]);
        }
        int bn = h * HID;
#pragma unroll
        for (int ni = 0; ni < 8; ni++) {
            int col = bn + ni * 8 + 2 * qid;
            if (gr0 < M) hp16[((size_t)gr0 * L1F + col) / 2] = __floats2half2_rn(c2[ni][0], c2[ni][1]);
            if (gr1 < M) hp16[((size_t)gr1 * L1F + col) / 2] = __floats2half2_rn(c2[ni][2], c2[ni][3]);
        }
        float u0 = c2[8][0] + c2[8][1];
        float u1 = c2[8][2] + c2[8][3];
        if (qid == 0) {
            if (gr0 < M) as_[(size_t)gr0 * HEADS + h] = u0;
            if (gr1 < M) as_[(size_t)gr1 * HEADS + h] = u1;
        } else if (qid == 1) {
            if (gr0 < M) ad_[(size_t)gr0 * HEADS + h] = u0;
            if (gr1 < M) ad_[(size_t)gr1 * HEADS + h] = u1;
        }
    }
}

// ---------------- layer-2 fp16 GEMM with in-MMA dots --------------------------
template <int NT, int KC>
__global__ __launch_bounds__(256, 3)
void hgemm_k(const __half* __restrict__ A, const __half* __restrict__ Bt,
             int M,
             __half2* __restrict__ hp16,
             float* __restrict__ as_, float* __restrict__ ad_) {
    constexpr int K = KC;
    constexpr int NTE = NT + 8;
    constexpr int NI = NTE / 8;
    constexpr int AST = 128 * 40;
    constexpr int BST = NTE * 40;
    constexpr int NB4 = NTE * 4;

    extern __shared__ __half smh[];
    __half* Asm = smh;
    __half* Bsm = smh + 2 * AST;
    int tid = threadIdx.x;
    int wid = tid >> 5, lane = tid & 31;
    int grp = lane >> 2, qid = lane & 3;
    int bm = blockIdx.y * 128;
    int hidx = blockIdx.x;
    const __half* Bth = Bt + (size_t)hidx * NTE * K;

    auto ldt = [&](int b, int k0) {
        __half* Ab = Asm + b * AST;
        __half* Bb = Bsm + b * BST;
#pragma unroll
        for (int t = 0; t < 2; t++) {
            int idx = tid + t * 256;
            int row = idx >> 2, c4 = idx & 3;
            int gm = bm + row;
            cp16h(Ab + row * 40 + c4 * 8, A + (size_t)gm * K + k0 + c4 * 8, gm < M);
        }
#pragma unroll
        for (int t = 0; t < (NB4 + 255) / 256; t++) {
            int idx = tid + t * 256;
            if (idx < NB4) {
                int n = idx >> 2, c4 = idx & 3;
                cp16h(Bb + n * 40 + c4 * 8, Bth + (size_t)n * K + k0 + c4 * 8, true);
            }
        }
    };

    float c[NI][4] = {};
    constexpr int nk = K >> 5;
    ldt(0, 0);
    CP_COMMIT();

    for (int t = 0; t < nk; t++) {
        if (t + 1 < nk) {
            ldt((t + 1) & 1, (t + 1) << 5);
            CP_COMMIT();
            CP_WAIT(1);
        } else {
            CP_WAIT(0);
        }
        __syncthreads();
        const __half* Ab = Asm + (t & 1) * AST;
        const __half* Bb = Bsm + (t & 1) * BST;
#pragma unroll
        for (int kk = 0; kk < 32; kk += 16) {
            uint32_t a[4], b[NI][2];
            int r = wid * 16 + grp;
            a[0] = *(const uint32_t*)&Ab[r * 40 + kk + 2 * qid];
            a[1] = *(const uint32_t*)&Ab[(r + 8) * 40 + kk + 2 * qid];
            a[2] = *(const uint32_t*)&Ab[r * 40 + kk + 2 * qid + 8];
            a[3] = *(const uint32_t*)&Ab[(r + 8) * 40 + kk + 2 * qid + 8];
#pragma unroll
            for (int ni = 0; ni < NI; ni++) {
                int cn = ni * 8 + grp;
                b[ni][0] = *(const uint32_t*)&Bb[cn * 40 + kk + 2 * qid];
                b[ni][1] = *(const uint32_t*)&Bb[cn * 40 + kk + 2 * qid + 8];
            }
#pragma unroll
            for (int ni = 0; ni < NI; ni++)
                MMA16(c[ni], a, b[ni]);
        }
        __syncthreads();
    }

    int gr0 = bm + wid * 16 + grp;
    int gr1 = gr0 + 8;
    int bn = hidx * NT;
#pragma unroll
    for (int ni = 0; ni < NI - 1; ni++) {
        int col = bn + ni * 8 + 2 * qid;
        if (gr0 < M) hp16[((size_t)gr0 * (HEADS * NT) + col) / 2] = __floats2half2_rn(c[ni][0], c[ni][1]);
        if (gr1 < M) hp16[((size_t)gr1 * (HEADS * NT) + col) / 2] = __floats2half2_rn(c[ni][2], c[ni][3]);
    }
    {
        float u0 = c[NI - 1][0] + c[NI - 1][1];
        float u1 = c[NI - 1][2] + c[NI - 1][3];
        if (qid == 0) {
            if (gr0 < M) as_[(size_t)gr0 * HEADS + hidx] = u0;
            if (gr1 < M) as_[(size_t)gr1 * HEADS + hidx] = u1;
        } else if (qid == 1) {
            if (gr0 < M) ad_[(size_t)gr0 * HEADS + hidx] = u0;
            if (gr1 < M) ad_[(size_t)gr1 * HEADS + hidx] = u1;
        }
    }
}

// ---------------- layer-1 aggregation: thread-per-(node,octet) -----------------
__global__ __launch_bounds__(320)
void gat_aggr1_k(const int4* __restrict__ hp16,
                 const float* __restrict__ as_,
                 const float* __restrict__ ad_,
                 const float* __restrict__ bias,
                 __half* __restrict__ out) {
    const int NO8 = L1F / 8;   // 40
    int t = blockIdx.x * 320 + threadIdx.x;
    int node = t / NO8, oct = t % NO8;
    if (node >= NN) return;
    int h = oct >> 3;
    int r0 = g_rowptr[node], r1 = g_rowptr[node + 1];
    float adv = ad_[node * HEADS + h];

    float acc[8] = {};
    float sl = 0.f;

#pragma unroll 4
    for (int j = r0; j < r1; j++) {
        int s = __ldg(&g_csrc[j]);
        float e = __ldg(&as_[s * HEADS + h]) + adv;
        e = (e > 0.f) ? e : 0.2f * e;
        float a = __expf(e);
        sl += a;
        int4 p = __ldg(hp16 + (size_t)s * NO8 + oct);
        float2 f0 = __half22float2(*(__half2*)&p.x);
        float2 f1 = __half22float2(*(__half2*)&p.y);
        float2 f2 = __half22float2(*(__half2*)&p.z);
        float2 f3 = __half22float2(*(__half2*)&p.w);
        acc[0] += a * f0.x; acc[1] += a * f0.y;
        acc[2] += a * f1.x; acc[3] += a * f1.y;
        acc[4] += a * f2.x; acc[5] += a * f2.y;
        acc[6] += a * f3.x; acc[7] += a * f3.y;
    }

    float inv = 1.f / (sl + 1e-16f);
    __half2 hh[4];
#pragma unroll
    for (int k = 0; k < 4; k++) {
        float va = acc[2 * k] * inv + bias[oct * 8 + 2 * k];
        float vb = acc[2 * k + 1] * inv + bias[oct * 8 + 2 * k + 1];
        va = (va > 0.f) ? va : (__expf(va) - 1.f);
        vb = (vb > 0.f) ? vb : (__expf(vb) - 1.f);
        hh[k] = __floats2half2_rn(va, vb);
    }
    int4 st;
    st.x = *(int*)&hh[0]; st.y = *(int*)&hh[1];
    st.z = *(int*)&hh[2]; st.w = *(int*)&hh[3];
    *(int4*)(out + (size_t)node * L1F + oct * 8) = st;
}

// ---------------- layer-2 aggregation + finalize --------------------------------
__global__ void gat_aggr2fin_k(const int4* __restrict__ hp16,
                               const float* __restrict__ as_,
                               const float* __restrict__ ad_,
                               const float* __restrict__ b2,
                               float* __restrict__ logits) {
    const int C = CLS, NO8 = L2F / 8;
    __shared__ float sh[8][L2F];
    int w = (blockIdx.x * blockDim.x + threadIdx.x) >> 5;
    int wl = threadIdx.x >> 5;
    int lane = threadIdx.x & 31;
    if (w >= NN) return;
    int r0 = g_rowptr[w], r1 = g_rowptr[w + 1];

    const int o0 = lane;
    const bool v0 = o0 < NO8;
    const int h0 = v0 ? (o0 * 8) / C : 0;
    const float adv0 = v0 ? ad_[w * HEADS + h0] : 0.f;

    float acc0[8] = {};
    float sl0 = 0.f;

#pragma unroll 4
    for (int j = r0; j < r1; j++) {
        int s = __ldg(&g_csrc[j]);
        if (v0) {
            float e = __ldg(&as_[s * HEADS + h0]) + adv0;
            e = (e > 0.f) ? e : 0.2f * e;
            float a = __expf(e);
            sl0 += a;
            int4 p = __ldg(hp16 + (size_t)s * NO8 + o0);
            float2 f0 = __half22float2(*(__half2*)&p.x);
            float2 f1 = __half22float2(*(__half2*)&p.y);
            float2 f2 = __half22float2(*(__half2*)&p.z);
            float2 f3 = __half22float2(*(__half2*)&p.w);
            acc0[0] += a * f0.x; acc0[1] += a * f0.y;
            acc0[2] += a * f1.x; acc0[3] += a * f1.y;
            acc0[4] += a * f2.x; acc0[5] += a * f2.y;
            acc0[6] += a * f3.x; acc0[7] += a * f3.y;
        }
    }

    if (v0) {
        float inv = 1.f / (sl0 + 1e-16f);
#pragma unroll
        for (int k = 0; k < 8; k++) sh[wl][o0 * 8 + k] = acc0[k] * inv;
    }
    __syncwarp();

    int c0 = lane, c1 = lane + 32;
    bool has1 = (c1 < CLS);
    float a0 = 0.f, a1 = 0.f;
#pragma unroll
    for (int h = 0; h < HEADS; h++) a0 += sh[wl][h * CLS + c0];
    float v0f = a0 * (1.f / HEADS) + b2[c0];
    float v1f = 0.f;
    if (has1) {
#pragma unroll
        for (int h = 0; h < HEADS; h++) a1 += sh[wl][h * CLS + c1];
        v1f = a1 * (1.f / HEADS) + b2[c1];
    }
    float mx = has1 ? fmaxf(v0f, v1f) : v0f;
#pragma unroll
    for (int o = 16; o; o >>= 1) mx = fmaxf(mx, __shfl_xor_sync(0xFFFFFFFFu, mx, o));
    float se = __expf(v0f - mx) + (has1 ? __expf(v1f - mx) : 0.f);
#pragma unroll
    for (int o = 16; o; o >>= 1) se += __shfl_xor_sync(0xFFFFFFFFu, se, o);
    float lse = logf(se) + mx;
    logits[(size_t)w * CLS + c0] = v0f - lse;
    if (has1) logits[(size_t)w * CLS + c1] = v1f - lse;
}

// ---------------- host ------------------------------------------------------------
#define HSMEM_L2 ((2 * 128 * 40 + 2 * (CLS + 8) * 40) * 2)

extern "C" void kernel_launch(void* const* d_in, const int* in_sizes, int n_in,
                              void* d_out, int out_size) {
    const float* x     = (const float*)d_in[0];
    const void*  ei    = d_in[1];
    const float* emb_W = (const float*)d_in[2];
    const float* emb_b = (const float*)d_in[3];
    const float* W1    = (const float*)d_in[4];
    const float* at_s1 = (const float*)d_in[5];
    const float* at_d1 = (const float*)d_in[6];
    const float* b1    = (const float*)d_in[7];
    const float* W2    = (const float*)d_in[8];
    const float* at_s2 = (const float*)d_in[9];
    const float* at_d2 = (const float*)d_in[10];
    const float* b2    = (const float*)d_in[11];

    float* outp   = (float*)d_out;
    float* emb    = outp;
    float* logits = outp + (size_t)NN * HID;

    float *as1, *ad1, *as2, *ad2;
    __half *o1h, *w1t, *w2t;
    int4* hp16;
    cudaGetSymbolAddress((void**)&as1,  g_as1);
    cudaGetSymbolAddress((void**)&ad1,  g_ad1);
    cudaGetSymbolAddress((void**)&as2,  g_as2);
    cudaGetSymbolAddress((void**)&ad2,  g_ad2);
    cudaGetSymbolAddress((void**)&o1h,  g_o1h);
    cudaGetSymbolAddress((void**)&w1t,  g_w1t);
    cudaGetSymbolAddress((void**)&w2t,  g_w2t);
    cudaGetSymbolAddress((void**)&hp16, g_hp16);

    // one-time handles (host-side only; no device allocation)
    static cudaStream_t side = nullptr;
    static cudaEvent_t ev_fork = nullptr, ev_join = nullptr;
    static int inited = 0;
    if (!inited) {
        cudaStreamCreateWithFlags(&side, cudaStreamNonBlocking);
        cudaEventCreateWithFlags(&ev_fork, cudaEventDisableTiming);
        cudaEventCreateWithFlags(&ev_join, cudaEventDisableTiming);
        cudaFuncSetAttribute(fused_emb_l1_k, cudaFuncAttributeMaxDynamicSharedMemorySize, FUSED_SMEM);
        cudaFuncSetAttribute(hgemm_k<CLS, L1F>, cudaFuncAttributeMaxDynamicSharedMemorySize, HSMEM_L2);
        inited = 1;
    }

    const int T = 256;
    const int MB = (NN + 127) / 128;

    // main stream: detect + prep, then fork
    detect_dtype_k<<<1, 32>>>(ei);
    prep_k<<<(SEGT + T - 1) / T, T>>>(W1, W2, at_s1, at_d1, at_s2, at_d2);
    cudaEventRecord(ev_fork, 0);

    // side stream: CSR build (depends on detect + prep's cnt/off init)
    cudaStreamWaitEvent(side, ev_fork, 0);
    hist_k<<<(ET + T - 1) / T, T, 0, side>>>(ei);
    blockscan_k<<<NB, 256, 0, side>>>();
    bscan2_k<<<1, 256, 0, side>>>();
    addoff_k<<<(NN + T - 1) / T, T, 0, side>>>();
    scatter_k<<<(ET + T - 1) / T, T, 0, side>>>(ei);
    cudaEventRecord(ev_join, side);

    // main stream: fused emb + layer-1 GEMM (overlaps the CSR chain)
    fused_emb_l1_k<<<MB, 256, FUSED_SMEM>>>(
        x, emb_W, emb, emb_b, w1t, (__half2*)hp16, as1, ad1, NN);

    // join, then the dependent tail
    cudaStreamWaitEvent(0, ev_join, 0);
    gat_aggr1_k<<<(NN * 40 + 319) / 320, 320>>>(hp16, as1, ad1, b1, o1h);
    hgemm_k<CLS, L1F><<<dim3(HEADS, MB), 256, HSMEM_L2>>>(
        o1h, w2t, NN, (__half2*)hp16, as2, ad2);
    gat_aggr2fin_k<<<(NN * 32 + T - 1) / T, T>>>(hp16, as2, ad2, b2, logits);
}